// round 3
// baseline (speedup 1.0000x reference)
#include <cuda_runtime.h>
#include <cuda_bf16.h>

#define NN   50000
#define NE   800000
#define ETOT (NE + NN)   // edges + self loops
#define IN   128
#define C1   256         // HEADS*HIDDEN
#define H1   4
#define F1   64
#define C2   32
#define SCAN_B 512
#define NB   ((NN + SCAN_B - 1) / SCAN_B)   // 98

// ---------------- scratch (static device globals; no allocation) ----------------
__device__ float g_h1 [NN * C1];   // layer1 features (x@W1)
__device__ float g_act[NN * C1];   // elu(gat1 output)
__device__ float g_h2 [NN * C2];   // layer2 features (act@W2)
__device__ float g_as1[NN * H1];
__device__ float g_ad1[NN * H1];
__device__ float g_as2[NN];
__device__ float g_ad2[NN];
__device__ int   g_deg[NN];
__device__ int   g_off[NN + 1];
__device__ int   g_pos[NN];
__device__ int   g_bsum[128];
__device__ int   g_boff[128];
__device__ int   g_csr[ETOT];      // src node id per CSR slot (grouped by dst)
__device__ int   g_stride;         // 1 = int32 edge_index, 2 = int64 edge_index

__device__ __forceinline__ float lrelu(float v) { return v > 0.f ? v : 0.2f * v; }

// ---------------- edge_index dtype detection ----------------
// int64 little-endian with values < 2^31 looks like [v,0,v,0,...] when viewed
// as int32. If the first 1024 odd words are ALL zero -> int64 (stride 2).
__global__ void k_detect(const int* __restrict__ p) {
    __shared__ int nz[256];
    int t = threadIdx.x;
    int acc = 0;
#pragma unroll
    for (int j = 0; j < 4; j++) acc |= p[2 * (t + 256 * j) + 1];
    nz[t] = acc;
    __syncthreads();
    for (int st = 128; st > 0; st >>= 1) {
        if (t < st) nz[t] |= nz[t + st];
        __syncthreads();
    }
    if (t == 0) g_stride = (nz[0] == 0) ? 2 : 1;
}

// ---------------- CSR build ----------------
__global__ void k_zero_deg() {
    int i = blockIdx.x * blockDim.x + threadIdx.x;
    if (i < NN) g_deg[i] = 0;
}

__global__ void k_count(const int* __restrict__ ei) {
    int e = blockIdx.x * blockDim.x + threadIdx.x;
    if (e >= ETOT) return;
    int st = g_stride;
    int d = (e < NE) ? ei[(NE + e) * st] : (e - NE);
    atomicAdd(&g_deg[d], 1);
}

__global__ void k_scan_local() {
    __shared__ int s[SCAN_B];
    int i = blockIdx.x * SCAN_B + threadIdx.x;
    int v = (i < NN) ? g_deg[i] : 0;
    s[threadIdx.x] = v;
    __syncthreads();
    for (int st = 1; st < SCAN_B; st <<= 1) {
        int t = (threadIdx.x >= st) ? s[threadIdx.x - st] : 0;
        __syncthreads();
        s[threadIdx.x] += t;
        __syncthreads();
    }
    if (i < NN) g_off[i] = s[threadIdx.x] - v;     // exclusive
    if (threadIdx.x == SCAN_B - 1) g_bsum[blockIdx.x] = s[SCAN_B - 1];
}

__global__ void k_scan_bsum() {
    __shared__ int s[128];
    int v = (threadIdx.x < NB) ? g_bsum[threadIdx.x] : 0;
    s[threadIdx.x] = v;
    __syncthreads();
    for (int st = 1; st < 128; st <<= 1) {
        int t = (threadIdx.x >= st) ? s[threadIdx.x - st] : 0;
        __syncthreads();
        s[threadIdx.x] += t;
        __syncthreads();
    }
    if (threadIdx.x < NB) g_boff[threadIdx.x] = s[threadIdx.x] - v;  // exclusive
}

__global__ void k_scan_add() {
    int i = blockIdx.x * SCAN_B + threadIdx.x;
    if (i < NN) {
        int o = g_off[i] + g_boff[blockIdx.x];
        g_off[i] = o;
        g_pos[i] = o;
    }
    if (i == 0) g_off[NN] = ETOT;
}

__global__ void k_fill(const int* __restrict__ ei) {
    int e = blockIdx.x * blockDim.x + threadIdx.x;
    if (e >= ETOT) return;
    int st = g_stride;
    int s, d;
    if (e < NE) { s = ei[e * st]; d = ei[(NE + e) * st]; }
    else        { s = d = e - NE; }
    int slot = atomicAdd(&g_pos[d], 1);
    g_csr[slot] = s;
}

// ---------------- GEMM1: g_h1 = x @ W1   (M=50000, K=128, N=256) ----------------
__global__ void __launch_bounds__(256) k_gemm1(const float* __restrict__ x,
                                               const float* __restrict__ W1) {
    __shared__ float sx[IN * 32];   // [k][i], 16KB
    int m0 = blockIdx.x * 32;
    int tid = threadIdx.x;
    for (int idx = tid; idx < 32 * IN; idx += 256) {
        int i = idx / IN, k = idx % IN;
        sx[k * 32 + i] = (m0 + i < NN) ? x[(m0 + i) * IN + k] : 0.f;
    }
    __syncthreads();
    float acc[32];
#pragma unroll
    for (int i = 0; i < 32; i++) acc[i] = 0.f;
#pragma unroll 4
    for (int k = 0; k < IN; k++) {
        float wv = W1[k * C1 + tid];
        const float4* xr = (const float4*)&sx[k * 32];
#pragma unroll
        for (int j = 0; j < 8; j++) {
            float4 v = xr[j];
            acc[4 * j + 0] = fmaf(v.x, wv, acc[4 * j + 0]);
            acc[4 * j + 1] = fmaf(v.y, wv, acc[4 * j + 1]);
            acc[4 * j + 2] = fmaf(v.z, wv, acc[4 * j + 2]);
            acc[4 * j + 3] = fmaf(v.w, wv, acc[4 * j + 3]);
        }
    }
#pragma unroll
    for (int i = 0; i < 32; i++)
        if (m0 + i < NN) g_h1[(m0 + i) * C1 + tid] = acc[i];
}

// ---------------- alpha1: per-node attention dots ----------------
__global__ void k_alpha1(const float* __restrict__ av_s, const float* __restrict__ av_d) {
    int warp = threadIdx.x >> 5;
    int n = blockIdx.x * 8 + warp;
    if (n >= NN) return;
    int lane = threadIdx.x & 31;
    int h = lane >> 3, fl = lane & 7;
    const float* hr = &g_h1[n * C1 + h * F1];
    float ss = 0.f, sd = 0.f;
#pragma unroll
    for (int i = 0; i < 8; i++) {
        int f = fl + 8 * i;
        float hv = hr[f];
        ss = fmaf(hv, av_s[h * F1 + f], ss);
        sd = fmaf(hv, av_d[h * F1 + f], sd);
    }
#pragma unroll
    for (int o = 4; o > 0; o >>= 1) {
        ss += __shfl_down_sync(0xffffffffu, ss, o);
        sd += __shfl_down_sync(0xffffffffu, sd, o);
    }
    if (fl == 0) { g_as1[n * H1 + h] = ss; g_ad1[n * H1 + h] = sd; }
}

// ---------------- agg1: block per dst node, softmax + weighted gather ----------------
__global__ void __launch_bounds__(256) k_agg1(const float* __restrict__ b1) {
    int n   = blockIdx.x;
    int tid = threadIdx.x;
    int off = g_off[n];
    int deg = g_off[n + 1] - off;
    int hf  = tid >> 6;   // head of this feature column

    __shared__ float4 sred[256];
    __shared__ int    s_src[64];
    __shared__ float  s_w[64 * 4];
    __shared__ float  s_m[4];
    __shared__ float  s_sum[4];

    const float4 adv = *(const float4*)&g_ad1[n * 4];

    // pass 1: per-head max over incoming edges
    float4 m = make_float4(-1e30f, -1e30f, -1e30f, -1e30f);
    for (int i = tid; i < deg; i += 256) {
        int s = g_csr[off + i];
        const float4 av = *(const float4*)&g_as1[s * 4];
        m.x = fmaxf(m.x, lrelu(av.x + adv.x));
        m.y = fmaxf(m.y, lrelu(av.y + adv.y));
        m.z = fmaxf(m.z, lrelu(av.z + adv.z));
        m.w = fmaxf(m.w, lrelu(av.w + adv.w));
    }
    sred[tid] = m;
    __syncthreads();
    for (int st = 128; st > 0; st >>= 1) {
        if (tid < st) {
            float4 a = sred[tid], o = sred[tid + st];
            a.x = fmaxf(a.x, o.x); a.y = fmaxf(a.y, o.y);
            a.z = fmaxf(a.z, o.z); a.w = fmaxf(a.w, o.w);
            sred[tid] = a;
        }
        __syncthreads();
    }
    if (tid < 4) s_m[tid] = ((float*)&sred[0])[tid];
    __syncthreads();
    float m0 = s_m[0], m1 = s_m[1], m2 = s_m[2], m3 = s_m[3];

    // pass 1b: per-head sum of exp(l - max)
    float4 sm = make_float4(0.f, 0.f, 0.f, 0.f);
    for (int i = tid; i < deg; i += 256) {
        int s = g_csr[off + i];
        const float4 av = *(const float4*)&g_as1[s * 4];
        sm.x += __expf(lrelu(av.x + adv.x) - m0);
        sm.y += __expf(lrelu(av.y + adv.y) - m1);
        sm.z += __expf(lrelu(av.z + adv.z) - m2);
        sm.w += __expf(lrelu(av.w + adv.w) - m3);
    }
    __syncthreads();
    sred[tid] = sm;
    __syncthreads();
    for (int st = 128; st > 0; st >>= 1) {
        if (tid < st) {
            float4 a = sred[tid], o = sred[tid + st];
            a.x += o.x; a.y += o.y; a.z += o.z; a.w += o.w;
            sred[tid] = a;
        }
        __syncthreads();
    }
    if (tid < 4) s_sum[tid] = ((float*)&sred[0])[tid];
    __syncthreads();

    // pass 2: weighted feature aggregation (feature = tid).
    // Tile = 64 edges: 64 edges * 4 heads = 256 threads prep the weights.
    float acc = 0.f;
    for (int t0 = 0; t0 < deg; t0 += 64) {
        int cnt = min(64, deg - t0);
        int i = tid >> 2, h = tid & 3;
        if (i < cnt) {
            int s = g_csr[off + t0 + i];
            if (h == 0) s_src[i] = s;
            float adh = (h == 0) ? adv.x : (h == 1) ? adv.y : (h == 2) ? adv.z : adv.w;
            float l = lrelu(g_as1[s * 4 + h] + adh);
            s_w[(i << 2) + h] = __expf(l - s_m[h]);
        }
        __syncthreads();
#pragma unroll 4
        for (int j = 0; j < cnt; j++) {
            acc = fmaf(g_h1[s_src[j] * C1 + tid], s_w[(j << 2) + hf], acc);
        }
        __syncthreads();
    }
    float o = acc / (s_sum[hf] + 1e-16f) + b1[tid];
    g_act[n * C1 + tid] = (o > 0.f) ? o : expm1f(o);   // elu
}

// ---------------- GEMM2: g_h2 = g_act @ W2  (M=50000, K=256, N=32) ----------------
__global__ void __launch_bounds__(256) k_gemm2(const float* __restrict__ W2) {
    __shared__ float sx[C1 * 32];   // [k][i], 32KB
    int m0 = blockIdx.x * 32;
    int tid = threadIdx.x;
    for (int idx = tid; idx < 32 * C1; idx += 256) {
        int i = idx / C1, k = idx % C1;
        sx[k * 32 + i] = (m0 + i < NN) ? g_act[(m0 + i) * C1 + k] : 0.f;
    }
    __syncthreads();
    int col = tid & 31, ir = tid >> 5;   // ir in 0..7, 4 nodes per thread
    float acc[4] = {0.f, 0.f, 0.f, 0.f};
#pragma unroll 4
    for (int k = 0; k < C1; k++) {
        float wv = W2[k * C2 + col];
        const float4 v = *(const float4*)&sx[k * 32 + ir * 4];
        acc[0] = fmaf(v.x, wv, acc[0]);
        acc[1] = fmaf(v.y, wv, acc[1]);
        acc[2] = fmaf(v.z, wv, acc[2]);
        acc[3] = fmaf(v.w, wv, acc[3]);
    }
#pragma unroll
    for (int j = 0; j < 4; j++) {
        int node = m0 + ir * 4 + j;
        if (node < NN) g_h2[node * C2 + col] = acc[j];
    }
}

// ---------------- alpha2 ----------------
__global__ void k_alpha2(const float* __restrict__ av_s, const float* __restrict__ av_d) {
    int warp = threadIdx.x >> 5;
    int n = blockIdx.x * 8 + warp;
    if (n >= NN) return;
    int lane = threadIdx.x & 31;
    float hv = g_h2[n * C2 + lane];
    float ss = hv * av_s[lane];
    float sd = hv * av_d[lane];
#pragma unroll
    for (int o = 16; o > 0; o >>= 1) {
        ss += __shfl_down_sync(0xffffffffu, ss, o);
        sd += __shfl_down_sync(0xffffffffu, sd, o);
    }
    if (lane == 0) { g_as2[n] = ss; g_ad2[n] = sd; }
}

// ---------------- agg2: warp per dst node ----------------
__global__ void k_agg2(const float* __restrict__ b2, float* __restrict__ out) {
    int warp = threadIdx.x >> 5;
    int n = blockIdx.x * 8 + warp;
    if (n >= NN) return;
    int lane = threadIdx.x & 31;
    int off = g_off[n], deg = g_off[n + 1] - off;
    float adn = g_ad2[n];

    float m = -1e30f;
    for (int i = lane; i < deg; i += 32)
        m = fmaxf(m, lrelu(g_as2[g_csr[off + i]] + adn));
#pragma unroll
    for (int o = 16; o > 0; o >>= 1) m = fmaxf(m, __shfl_xor_sync(0xffffffffu, m, o));

    float sm = 0.f;
    for (int i = lane; i < deg; i += 32)
        sm += __expf(lrelu(g_as2[g_csr[off + i]] + adn) - m);
#pragma unroll
    for (int o = 16; o > 0; o >>= 1) sm += __shfl_xor_sync(0xffffffffu, sm, o);

    float acc = 0.f;
    for (int i = 0; i < deg; i++) {
        int s = g_csr[off + i];                      // broadcast load
        float w = __expf(lrelu(g_as2[s] + adn) - m); // broadcast load, redundant compute
        acc = fmaf(g_h2[s * C2 + lane], w, acc);     // coalesced 128B row
    }
    out[n * C2 + lane] = acc / (sm + 1e-16f) + b2[lane];
}

// ---------------- launch ----------------
extern "C" void kernel_launch(void* const* d_in, const int* in_sizes, int n_in,
                              void* d_out, int out_size) {
    const float* x    = (const float*)d_in[0];
    const int*   ei   = (const int*)d_in[1];   // int32 (JAX x64 disabled) or int64 (detected)
    const float* W1   = (const float*)d_in[2];
    const float* as1v = (const float*)d_in[3];
    const float* ad1v = (const float*)d_in[4];
    const float* b1   = (const float*)d_in[5];
    const float* W2   = (const float*)d_in[6];
    const float* as2v = (const float*)d_in[7];
    const float* ad2v = (const float*)d_in[8];
    const float* b2   = (const float*)d_in[9];
    float*       out  = (float*)d_out;

    // detect edge_index element width, then CSR build (reused by both layers)
    k_detect<<<1, 256>>>(ei);
    k_zero_deg<<<(NN + 255) / 256, 256>>>();
    k_count<<<(ETOT + 255) / 256, 256>>>(ei);
    k_scan_local<<<NB, SCAN_B>>>();
    k_scan_bsum<<<1, 128>>>();
    k_scan_add<<<NB, SCAN_B>>>();
    k_fill<<<(ETOT + 255) / 256, 256>>>(ei);

    // layer 1
    k_gemm1<<<(NN + 31) / 32, 256>>>(x, W1);
    k_alpha1<<<(NN + 7) / 8, 256>>>(as1v, ad1v);
    k_agg1<<<NN, 256>>>(b1);

    // layer 2
    k_gemm2<<<(NN + 31) / 32, 256>>>(W2);
    k_alpha2<<<(NN + 7) / 8, 256>>>(as2v, ad2v);
    k_agg2<<<(NN + 7) / 8, 256>>>(b2, out);
}

// round 4
// speedup vs baseline: 1.3930x; 1.3930x over previous
#include <cuda_runtime.h>
#include <cuda_bf16.h>

#define NN   50000
#define NE   800000
#define ETOT (NE + NN)   // edges + self loops
#define IN   128
#define C1   256         // HEADS*HIDDEN
#define H1   4
#define F1   64
#define C2   32
#define SCAN_B 512
#define NB   ((NN + SCAN_B - 1) / SCAN_B)   // 98

// ---------------- scratch (static device globals; no allocation) ----------------
__device__ float g_h1 [NN * C1];   // layer1 features (x@W1)
__device__ float g_act[NN * C1];   // elu(gat1 output)
__device__ float g_h2 [NN * C2];   // layer2 features (act@W2)
__device__ float g_as1[NN * H1];
__device__ float g_ad1[NN * H1];
__device__ float g_as2[NN];
__device__ float g_ad2[NN];
__device__ float g_gm1[4];         // global per-head max of g_as1
__device__ float g_gm2[1];         // global max of g_as2
__device__ int   g_deg[NN];
__device__ int   g_off[NN + 1];
__device__ int   g_pos[NN];
__device__ int   g_bsum[128];
__device__ int   g_boff[128];
__device__ int   g_csr[ETOT];      // src node id per CSR slot (grouped by dst)
__device__ int   g_stride;         // 1 = int32 edge_index, 2 = int64 edge_index

__device__ __forceinline__ float lrelu(float v) { return v > 0.f ? v : 0.2f * v; }

// ---------------- edge_index dtype detection ----------------
__global__ void k_detect(const int* __restrict__ p) {
    __shared__ int nz[256];
    int t = threadIdx.x;
    int acc = 0;
#pragma unroll
    for (int j = 0; j < 4; j++) acc |= p[2 * (t + 256 * j) + 1];
    nz[t] = acc;
    __syncthreads();
    for (int st = 128; st > 0; st >>= 1) {
        if (t < st) nz[t] |= nz[t + st];
        __syncthreads();
    }
    if (t == 0) g_stride = (nz[0] == 0) ? 2 : 1;
}

// ---------------- CSR build ----------------
__global__ void k_zero_deg() {
    int i = blockIdx.x * blockDim.x + threadIdx.x;
    if (i < NN) g_deg[i] = 0;
}

__global__ void k_count(const int* __restrict__ ei) {
    int e = blockIdx.x * blockDim.x + threadIdx.x;
    if (e >= ETOT) return;
    int st = g_stride;
    int d = (e < NE) ? ei[(NE + e) * st] : (e - NE);
    atomicAdd(&g_deg[d], 1);
}

__global__ void k_scan_local() {
    __shared__ int s[SCAN_B];
    int i = blockIdx.x * SCAN_B + threadIdx.x;
    int v = (i < NN) ? g_deg[i] : 0;
    s[threadIdx.x] = v;
    __syncthreads();
    for (int st = 1; st < SCAN_B; st <<= 1) {
        int t = (threadIdx.x >= st) ? s[threadIdx.x - st] : 0;
        __syncthreads();
        s[threadIdx.x] += t;
        __syncthreads();
    }
    if (i < NN) g_off[i] = s[threadIdx.x] - v;     // exclusive
    if (threadIdx.x == SCAN_B - 1) g_bsum[blockIdx.x] = s[SCAN_B - 1];
}

__global__ void k_scan_bsum() {
    __shared__ int s[128];
    int v = (threadIdx.x < NB) ? g_bsum[threadIdx.x] : 0;
    s[threadIdx.x] = v;
    __syncthreads();
    for (int st = 1; st < 128; st <<= 1) {
        int t = (threadIdx.x >= st) ? s[threadIdx.x - st] : 0;
        __syncthreads();
        s[threadIdx.x] += t;
        __syncthreads();
    }
    if (threadIdx.x < NB) g_boff[threadIdx.x] = s[threadIdx.x] - v;  // exclusive
}

__global__ void k_scan_add() {
    int i = blockIdx.x * SCAN_B + threadIdx.x;
    if (i < NN) {
        int o = g_off[i] + g_boff[blockIdx.x];
        g_off[i] = o;
        g_pos[i] = o;
    }
    if (i == 0) g_off[NN] = ETOT;
}

__global__ void k_fill(const int* __restrict__ ei) {
    int e = blockIdx.x * blockDim.x + threadIdx.x;
    if (e >= ETOT) return;
    int st = g_stride;
    int s, d;
    if (e < NE) { s = ei[e * st]; d = ei[(NE + e) * st]; }
    else        { s = d = e - NE; }
    int slot = atomicAdd(&g_pos[d], 1);
    g_csr[slot] = s;
}

// ---------------- GEMM1: g_h1 = x @ W1   (M=50000, K=128, N=256) ----------------
__global__ void __launch_bounds__(256) k_gemm1(const float* __restrict__ x,
                                               const float* __restrict__ W1) {
    __shared__ float sx[IN * 32];   // [k][i], 16KB
    int m0 = blockIdx.x * 32;
    int tid = threadIdx.x;
    for (int idx = tid; idx < 32 * IN; idx += 256) {
        int i = idx / IN, k = idx % IN;
        sx[k * 32 + i] = (m0 + i < NN) ? x[(m0 + i) * IN + k] : 0.f;
    }
    __syncthreads();
    float acc[32];
#pragma unroll
    for (int i = 0; i < 32; i++) acc[i] = 0.f;
#pragma unroll 4
    for (int k = 0; k < IN; k++) {
        float wv = W1[k * C1 + tid];
        const float4* xr = (const float4*)&sx[k * 32];
#pragma unroll
        for (int j = 0; j < 8; j++) {
            float4 v = xr[j];
            acc[4 * j + 0] = fmaf(v.x, wv, acc[4 * j + 0]);
            acc[4 * j + 1] = fmaf(v.y, wv, acc[4 * j + 1]);
            acc[4 * j + 2] = fmaf(v.z, wv, acc[4 * j + 2]);
            acc[4 * j + 3] = fmaf(v.w, wv, acc[4 * j + 3]);
        }
    }
#pragma unroll
    for (int i = 0; i < 32; i++)
        if (m0 + i < NN) g_h1[(m0 + i) * C1 + tid] = acc[i];
}

// ---------------- alpha1: per-node attention dots ----------------
__global__ void k_alpha1(const float* __restrict__ av_s, const float* __restrict__ av_d) {
    int warp = threadIdx.x >> 5;
    int n = blockIdx.x * 8 + warp;
    if (n >= NN) return;
    int lane = threadIdx.x & 31;
    int h = lane >> 3, fl = lane & 7;
    const float* hr = &g_h1[n * C1 + h * F1];
    float ss = 0.f, sd = 0.f;
#pragma unroll
    for (int i = 0; i < 8; i++) {
        int f = fl + 8 * i;
        float hv = hr[f];
        ss = fmaf(hv, av_s[h * F1 + f], ss);
        sd = fmaf(hv, av_d[h * F1 + f], sd);
    }
#pragma unroll
    for (int o = 4; o > 0; o >>= 1) {
        ss += __shfl_down_sync(0xffffffffu, ss, o);
        sd += __shfl_down_sync(0xffffffffu, sd, o);
    }
    if (fl == 0) { g_as1[n * H1 + h] = ss; g_ad1[n * H1 + h] = sd; }
}

// ---------------- global per-head max of g_as1 (single block) ----------------
__global__ void __launch_bounds__(1024) k_gmax1() {
    __shared__ float4 sr[1024];
    int t = threadIdx.x;
    float4 m = make_float4(-1e30f, -1e30f, -1e30f, -1e30f);
    for (int n = t; n < NN; n += 1024) {
        float4 v = *(const float4*)&g_as1[n * 4];
        m.x = fmaxf(m.x, v.x); m.y = fmaxf(m.y, v.y);
        m.z = fmaxf(m.z, v.z); m.w = fmaxf(m.w, v.w);
    }
    sr[t] = m;
    __syncthreads();
    for (int st = 512; st > 0; st >>= 1) {
        if (t < st) {
            float4 a = sr[t], o = sr[t + st];
            a.x = fmaxf(a.x, o.x); a.y = fmaxf(a.y, o.y);
            a.z = fmaxf(a.z, o.z); a.w = fmaxf(a.w, o.w);
            sr[t] = a;
        }
        __syncthreads();
    }
    if (t == 0) *(float4*)g_gm1 = sr[0];
}

// ---------------- agg1: SINGLE PASS softmax + weighted gather ----------------
// 128 threads, each handles 2 features (float2). Subtractor = global upper
// bound lrelu(gmax_h + ad[n,h]) >= per-node segment max (lrelu monotone),
// so exp <= 1 always and the normalized result is mathematically identical.
__global__ void __launch_bounds__(128) k_agg1(const float* __restrict__ b1) {
    int n   = blockIdx.x;
    int tid = threadIdx.x;
    int off = g_off[n];
    int deg = g_off[n + 1] - off;
    int hf  = tid >> 5;          // head of this feature pair (2*tid)/64
    int i   = tid >> 2;          // edge slot in prep (0..31)
    int h   = tid & 3;           // head in prep

    __shared__ int   s_src[32];
    __shared__ float s_w[32 * 4];
    __shared__ float s_red[128];

    const float4 adv = *(const float4*)&g_ad1[n * 4];
    const float4 gm  = *(const float4*)g_gm1;
    float adh = (h == 0) ? adv.x : (h == 1) ? adv.y : (h == 2) ? adv.z : adv.w;
    float gmh = (h == 0) ? gm.x  : (h == 1) ? gm.y  : (h == 2) ? gm.z  : gm.w;
    float Bh  = lrelu(gmh + adh);   // per (node, head) subtractor

    float wsum = 0.f;
    float2 acc = make_float2(0.f, 0.f);

    for (int t0 = 0; t0 < deg; t0 += 32) {
        int cnt = min(32, deg - t0);
        __syncthreads();   // protect s_w/s_src reuse across tiles
        if (i < cnt) {
            int s = g_csr[off + t0 + i];
            if (h == 0) s_src[i] = s;
            float w = __expf(lrelu(g_as1[s * 4 + h] + adh) - Bh);
            s_w[(i << 2) + h] = w;
            wsum += w;
        }
        __syncthreads();
#pragma unroll 4
        for (int j = 0; j < cnt; j++) {
            float2 v = ((const float2*)&g_h1[s_src[j] * C1])[tid];
            float  w = s_w[(j << 2) + hf];
            acc.x = fmaf(v.x, w, acc.x);
            acc.y = fmaf(v.y, w, acc.y);
        }
    }

    // reduce wsum per head (contributor head = tid&3; strides multiple of 4)
    s_red[tid] = wsum;
    __syncthreads();
    for (int st = 64; st >= 4; st >>= 1) {
        if (tid < st) s_red[tid] += s_red[tid + st];
        __syncthreads();
    }
    float denom = s_red[hf] + 1e-16f;

    float2 bb = ((const float2*)b1)[tid];
    float ox = acc.x / denom + bb.x;
    float oy = acc.y / denom + bb.y;
    ox = (ox > 0.f) ? ox : expm1f(ox);   // elu
    oy = (oy > 0.f) ? oy : expm1f(oy);
    ((float2*)&g_act[n * C1])[tid] = make_float2(ox, oy);
}

// ---------------- GEMM2: g_h2 = g_act @ W2  (M=50000, K=256, N=32) ----------------
__global__ void __launch_bounds__(256) k_gemm2(const float* __restrict__ W2) {
    __shared__ float sx[C1 * 32];   // [k][i], 32KB
    int m0 = blockIdx.x * 32;
    int tid = threadIdx.x;
    for (int idx = tid; idx < 32 * C1; idx += 256) {
        int i = idx / C1, k = idx % C1;
        sx[k * 32 + i] = (m0 + i < NN) ? g_act[(m0 + i) * C1 + k] : 0.f;
    }
    __syncthreads();
    int col = tid & 31, ir = tid >> 5;   // ir in 0..7, 4 nodes per thread
    float acc[4] = {0.f, 0.f, 0.f, 0.f};
#pragma unroll 4
    for (int k = 0; k < C1; k++) {
        float wv = W2[k * C2 + col];
        const float4 v = *(const float4*)&sx[k * 32 + ir * 4];
        acc[0] = fmaf(v.x, wv, acc[0]);
        acc[1] = fmaf(v.y, wv, acc[1]);
        acc[2] = fmaf(v.z, wv, acc[2]);
        acc[3] = fmaf(v.w, wv, acc[3]);
    }
#pragma unroll
    for (int j = 0; j < 4; j++) {
        int node = m0 + ir * 4 + j;
        if (node < NN) g_h2[node * C2 + col] = acc[j];
    }
}

// ---------------- alpha2 ----------------
__global__ void k_alpha2(const float* __restrict__ av_s, const float* __restrict__ av_d) {
    int warp = threadIdx.x >> 5;
    int n = blockIdx.x * 8 + warp;
    if (n >= NN) return;
    int lane = threadIdx.x & 31;
    float hv = g_h2[n * C2 + lane];
    float ss = hv * av_s[lane];
    float sd = hv * av_d[lane];
#pragma unroll
    for (int o = 16; o > 0; o >>= 1) {
        ss += __shfl_down_sync(0xffffffffu, ss, o);
        sd += __shfl_down_sync(0xffffffffu, sd, o);
    }
    if (lane == 0) { g_as2[n] = ss; g_ad2[n] = sd; }
}

// ---------------- global max of g_as2 (single block) ----------------
__global__ void __launch_bounds__(1024) k_gmax2() {
    __shared__ float sr[1024];
    int t = threadIdx.x;
    float m = -1e30f;
    for (int n = t; n < NN; n += 1024) m = fmaxf(m, g_as2[n]);
    sr[t] = m;
    __syncthreads();
    for (int st = 512; st > 0; st >>= 1) {
        if (t < st) sr[t] = fmaxf(sr[t], sr[t + st]);
        __syncthreads();
    }
    if (t == 0) g_gm2[0] = sr[0];
}

// ---------------- agg2: warp per dst node, SINGLE PASS ----------------
__global__ void k_agg2(const float* __restrict__ b2, float* __restrict__ out) {
    int warp = threadIdx.x >> 5;
    int n = blockIdx.x * 8 + warp;
    if (n >= NN) return;
    int lane = threadIdx.x & 31;
    int off = g_off[n], deg = g_off[n + 1] - off;
    float adn = g_ad2[n];
    float B = lrelu(g_gm2[0] + adn);   // upper bound on segment max

    float acc0 = 0.f, acc1 = 0.f, ws0 = 0.f, ws1 = 0.f;
    int i = 0;
    for (; i + 1 < deg; i += 2) {
        int s0 = g_csr[off + i], s1 = g_csr[off + i + 1];
        float w0 = __expf(lrelu(g_as2[s0] + adn) - B);
        float w1 = __expf(lrelu(g_as2[s1] + adn) - B);
        acc0 = fmaf(g_h2[s0 * C2 + lane], w0, acc0);
        acc1 = fmaf(g_h2[s1 * C2 + lane], w1, acc1);
        ws0 += w0; ws1 += w1;
    }
    if (i < deg) {
        int s = g_csr[off + i];
        float w = __expf(lrelu(g_as2[s] + adn) - B);
        acc0 = fmaf(g_h2[s * C2 + lane], w, acc0);
        ws0 += w;
    }
    out[n * C2 + lane] = (acc0 + acc1) / (ws0 + ws1 + 1e-16f) + b2[lane];
}

// ---------------- launch ----------------
extern "C" void kernel_launch(void* const* d_in, const int* in_sizes, int n_in,
                              void* d_out, int out_size) {
    const float* x    = (const float*)d_in[0];
    const int*   ei   = (const int*)d_in[1];   // int32 (JAX x64 disabled) or int64 (detected)
    const float* W1   = (const float*)d_in[2];
    const float* as1v = (const float*)d_in[3];
    const float* ad1v = (const float*)d_in[4];
    const float* b1   = (const float*)d_in[5];
    const float* W2   = (const float*)d_in[6];
    const float* as2v = (const float*)d_in[7];
    const float* ad2v = (const float*)d_in[8];
    const float* b2   = (const float*)d_in[9];
    float*       out  = (float*)d_out;

    // detect edge_index element width, then CSR build (reused by both layers)
    k_detect<<<1, 256>>>(ei);
    k_zero_deg<<<(NN + 255) / 256, 256>>>();
    k_count<<<(ETOT + 255) / 256, 256>>>(ei);
    k_scan_local<<<NB, SCAN_B>>>();
    k_scan_bsum<<<1, 128>>>();
    k_scan_add<<<NB, SCAN_B>>>();
    k_fill<<<(ETOT + 255) / 256, 256>>>(ei);

    // layer 1
    k_gemm1<<<(NN + 31) / 32, 256>>>(x, W1);
    k_alpha1<<<(NN + 7) / 8, 256>>>(as1v, ad1v);
    k_gmax1<<<1, 1024>>>();
    k_agg1<<<NN, 128>>>(b1);

    // layer 2
    k_gemm2<<<(NN + 31) / 32, 256>>>(W2);
    k_alpha2<<<(NN + 7) / 8, 256>>>(as2v, ad2v);
    k_gmax2<<<1, 1024>>>();
    k_agg2<<<(NN + 7) / 8, 256>>>(b2, out);
}

// round 5
// speedup vs baseline: 1.4443x; 1.0368x over previous
#include <cuda_runtime.h>
#include <cuda_bf16.h>

#define NN   50000
#define NE   800000
#define ETOT (NE + NN)   // edges + self loops
#define IN   128
#define C1   256         // HEADS*HIDDEN
#define H1   4
#define F1   64
#define C2   32
#define SCAN_B 512
#define NB   ((NN + SCAN_B - 1) / SCAN_B)   // 98

// ---------------- scratch (static device globals; no allocation) ----------------
__device__ float g_h1 [NN * C1];   // layer1 features (x@W1)
__device__ float g_act[NN * C1];   // elu(gat1 output)
__device__ float g_h2 [NN * C2];   // layer2 features (act@W2)
__device__ float g_as1[NN * H1];
__device__ float g_ad1[NN * H1];
__device__ float g_as2[NN];
__device__ float g_ad2[NN];
__device__ float g_gm1[4];         // global per-head max of g_as1
__device__ float g_gm2[1];         // global max of g_as2
__device__ int   g_deg[NN];
__device__ int   g_off[NN + 1];
__device__ int   g_pos[NN];
__device__ int   g_bsum[128];
__device__ int   g_boff[128];
__device__ int   g_csr[ETOT];      // src node id per CSR slot (grouped by dst)
__device__ int   g_stride;         // 1 = int32 edge_index, 2 = int64 edge_index

__device__ __forceinline__ float lrelu(float v) { return v > 0.f ? v : 0.2f * v; }

// ---------------- edge_index dtype detection ----------------
__global__ void k_detect(const int* __restrict__ p) {
    __shared__ int nz[256];
    int t = threadIdx.x;
    int acc = 0;
#pragma unroll
    for (int j = 0; j < 4; j++) acc |= p[2 * (t + 256 * j) + 1];
    nz[t] = acc;
    __syncthreads();
    for (int st = 128; st > 0; st >>= 1) {
        if (t < st) nz[t] |= nz[t + st];
        __syncthreads();
    }
    if (t == 0) g_stride = (nz[0] == 0) ? 2 : 1;
}

// ---------------- CSR build ----------------
__global__ void k_zero_deg() {
    int i = blockIdx.x * blockDim.x + threadIdx.x;
    if (i < NN) g_deg[i] = 0;
}

__global__ void k_count(const int* __restrict__ ei) {
    int e = blockIdx.x * blockDim.x + threadIdx.x;
    if (e >= ETOT) return;
    int st = g_stride;
    int d = (e < NE) ? ei[(NE + e) * st] : (e - NE);
    atomicAdd(&g_deg[d], 1);
}

__global__ void k_scan_local() {
    __shared__ int s[SCAN_B];
    int i = blockIdx.x * SCAN_B + threadIdx.x;
    int v = (i < NN) ? g_deg[i] : 0;
    s[threadIdx.x] = v;
    __syncthreads();
    for (int st = 1; st < SCAN_B; st <<= 1) {
        int t = (threadIdx.x >= st) ? s[threadIdx.x - st] : 0;
        __syncthreads();
        s[threadIdx.x] += t;
        __syncthreads();
    }
    if (i < NN) g_off[i] = s[threadIdx.x] - v;     // exclusive
    if (threadIdx.x == SCAN_B - 1) g_bsum[blockIdx.x] = s[SCAN_B - 1];
}

__global__ void k_scan_bsum() {
    __shared__ int s[128];
    int v = (threadIdx.x < NB) ? g_bsum[threadIdx.x] : 0;
    s[threadIdx.x] = v;
    __syncthreads();
    for (int st = 1; st < 128; st <<= 1) {
        int t = (threadIdx.x >= st) ? s[threadIdx.x - st] : 0;
        __syncthreads();
        s[threadIdx.x] += t;
        __syncthreads();
    }
    if (threadIdx.x < NB) g_boff[threadIdx.x] = s[threadIdx.x] - v;  // exclusive
}

__global__ void k_scan_add() {
    int i = blockIdx.x * SCAN_B + threadIdx.x;
    if (i < NN) {
        int o = g_off[i] + g_boff[blockIdx.x];
        g_off[i] = o;
        g_pos[i] = o;
    }
    if (i == 0) g_off[NN] = ETOT;
}

__global__ void k_fill(const int* __restrict__ ei) {
    int e = blockIdx.x * blockDim.x + threadIdx.x;
    if (e >= ETOT) return;
    int st = g_stride;
    int s, d;
    if (e < NE) { s = ei[e * st]; d = ei[(NE + e) * st]; }
    else        { s = d = e - NE; }
    int slot = atomicAdd(&g_pos[d], 1);
    g_csr[slot] = s;
}

// ---------------- GEMM1 + alpha1 fused:
// g_h1 = x @ W1 (M=50000, K=128, N=256); epilogue computes per-(node,head)
// dots with a_src1 / a_dst1 directly from the register tile via smem + shfl.
__global__ void __launch_bounds__(256) k_gemm1(const float* __restrict__ x,
                                               const float* __restrict__ W1,
                                               const float* __restrict__ av_s,
                                               const float* __restrict__ av_d) {
    __shared__ float sh[32 * 256];   // 32KB; first 16KB doubles as x-tile [k][i]
    float* sx = sh;
    int m0 = blockIdx.x * 32;
    int tid = threadIdx.x;
    for (int idx = tid; idx < 32 * IN; idx += 256) {
        int i = idx / IN, k = idx % IN;
        sx[k * 32 + i] = (m0 + i < NN) ? x[(m0 + i) * IN + k] : 0.f;
    }
    __syncthreads();
    float acc[32];
#pragma unroll
    for (int i = 0; i < 32; i++) acc[i] = 0.f;
#pragma unroll 4
    for (int k = 0; k < IN; k++) {
        float wv = W1[k * C1 + tid];
        const float4* xr = (const float4*)&sx[k * 32];
#pragma unroll
        for (int j = 0; j < 8; j++) {
            float4 v = xr[j];
            acc[4 * j + 0] = fmaf(v.x, wv, acc[4 * j + 0]);
            acc[4 * j + 1] = fmaf(v.y, wv, acc[4 * j + 1]);
            acc[4 * j + 2] = fmaf(v.z, wv, acc[4 * j + 2]);
            acc[4 * j + 3] = fmaf(v.w, wv, acc[4 * j + 3]);
        }
    }
    __syncthreads();   // done reading sx; sh will be overwritten
#pragma unroll
    for (int i = 0; i < 32; i++) {
        if (m0 + i < NN) g_h1[(m0 + i) * C1 + tid] = acc[i];
        sh[i * 256 + tid] = acc[i];
    }
    __syncthreads();

    // epilogue: warp w handles nodes w, w+8, w+16, w+24.
    // lane reads cols lane+32j (j=0..7); head of col = j>>1.
    int warp = tid >> 5, lane = tid & 31;
    float a_s[8], a_d[8];
#pragma unroll
    for (int j = 0; j < 8; j++) {
        a_s[j] = av_s[lane + 32 * j];
        a_d[j] = av_d[lane + 32 * j];
    }
#pragma unroll
    for (int r = 0; r < 4; r++) {
        int i = warp + 8 * r;
        float ps[4] = {0.f, 0.f, 0.f, 0.f};
        float pd[4] = {0.f, 0.f, 0.f, 0.f};
#pragma unroll
        for (int j = 0; j < 8; j++) {
            float v = sh[i * 256 + lane + 32 * j];
            int h = j >> 1;
            ps[h] = fmaf(v, a_s[j], ps[h]);
            pd[h] = fmaf(v, a_d[j], pd[h]);
        }
#pragma unroll
        for (int o = 16; o > 0; o >>= 1) {
#pragma unroll
            for (int h = 0; h < 4; h++) {
                ps[h] += __shfl_down_sync(0xffffffffu, ps[h], o);
                pd[h] += __shfl_down_sync(0xffffffffu, pd[h], o);
            }
        }
        if (lane == 0 && m0 + i < NN) {
#pragma unroll
            for (int h = 0; h < 4; h++) {
                g_as1[(m0 + i) * 4 + h] = ps[h];
                g_ad1[(m0 + i) * 4 + h] = pd[h];
            }
        }
    }
}

// ---------------- global per-head max of g_as1 (single block) ----------------
__global__ void __launch_bounds__(1024) k_gmax1() {
    __shared__ float4 sr[1024];
    int t = threadIdx.x;
    float4 m = make_float4(-1e30f, -1e30f, -1e30f, -1e30f);
    for (int n = t; n < NN; n += 1024) {
        float4 v = *(const float4*)&g_as1[n * 4];
        m.x = fmaxf(m.x, v.x); m.y = fmaxf(m.y, v.y);
        m.z = fmaxf(m.z, v.z); m.w = fmaxf(m.w, v.w);
    }
    sr[t] = m;
    __syncthreads();
    for (int st = 512; st > 0; st >>= 1) {
        if (t < st) {
            float4 a = sr[t], o = sr[t + st];
            a.x = fmaxf(a.x, o.x); a.y = fmaxf(a.y, o.y);
            a.z = fmaxf(a.z, o.z); a.w = fmaxf(a.w, o.w);
            sr[t] = a;
        }
        __syncthreads();
    }
    if (t == 0) *(float4*)g_gm1 = sr[0];
}

// ---------------- agg1: single pass, ping-pong tiles, 1 barrier/tile ----------------
__global__ void __launch_bounds__(128) k_agg1(const float* __restrict__ b1) {
    int n   = blockIdx.x;
    int tid = threadIdx.x;
    int off = g_off[n];
    int deg = g_off[n + 1] - off;
    int hf  = tid >> 5;          // head of this feature pair
    int i   = tid >> 2;          // edge slot in prep (0..31)
    int h   = tid & 3;           // head in prep

    __shared__ int   s_src[2][32];
    __shared__ float s_w[2][128];
    __shared__ float s4[16];     // [warp][head]

    const float4 adv = *(const float4*)&g_ad1[n * 4];
    const float4 gm  = *(const float4*)g_gm1;
    float adh = (h == 0) ? adv.x : (h == 1) ? adv.y : (h == 2) ? adv.z : adv.w;
    float gmh = (h == 0) ? gm.x  : (h == 1) ? gm.y  : (h == 2) ? gm.z  : gm.w;
    float Bh  = lrelu(gmh + adh);   // global upper bound on segment max

    float wsum = 0.f;
    float2 acc = make_float2(0.f, 0.f);

    // prep tile 0
    if (i < deg) {
        int s = g_csr[off + i];
        if (h == 0) s_src[0][i] = s;
        float w = __expf(lrelu(g_as1[s * 4 + h] + adh) - Bh);
        s_w[0][(i << 2) + h] = w;
        wsum += w;
    }
    __syncthreads();

    int nt = (deg + 31) >> 5;
    for (int t = 0; t < nt; t++) {
        int cur  = t & 1;
        int base = t << 5;
        int cnt  = min(32, deg - base);
        int nb   = base + 32;
        if (nb + i < deg && i < 32) {   // prep next tile into other buffer
            int s = g_csr[off + nb + i];
            if (h == 0) s_src[cur ^ 1][i] = s;
            float w = __expf(lrelu(g_as1[s * 4 + h] + adh) - Bh);
            s_w[cur ^ 1][(i << 2) + h] = w;
            wsum += w;
        }
#pragma unroll 4
        for (int j = 0; j < cnt; j++) {
            float2 v = ((const float2*)&g_h1[s_src[cur][j] * C1])[tid];
            float  w = s_w[cur][(j << 2) + hf];
            acc.x = fmaf(v.x, w, acc.x);
            acc.y = fmaf(v.y, w, acc.y);
        }
        __syncthreads();   // one barrier per tile
    }

    // reduce wsum per head: xor strides 16,8,4 preserve (lane & 3) == head
    wsum += __shfl_xor_sync(0xffffffffu, wsum, 16);
    wsum += __shfl_xor_sync(0xffffffffu, wsum, 8);
    wsum += __shfl_xor_sync(0xffffffffu, wsum, 4);
    int lane = tid & 31, warp = tid >> 5;
    if (lane < 4) s4[warp * 4 + lane] = wsum;
    __syncthreads();
    float denom = s4[hf] + s4[4 + hf] + s4[8 + hf] + s4[12 + hf] + 1e-16f;

    float2 bb = ((const float2*)b1)[tid];
    float ox = acc.x / denom + bb.x;
    float oy = acc.y / denom + bb.y;
    ox = (ox > 0.f) ? ox : expm1f(ox);   // elu
    oy = (oy > 0.f) ? oy : expm1f(oy);
    ((float2*)&g_act[n * C1])[tid] = make_float2(ox, oy);
}

// ---------------- GEMM2 + alpha2 fused: g_h2 = g_act @ W2 (M=50000,K=256,N=32) ----------------
__global__ void __launch_bounds__(256) k_gemm2(const float* __restrict__ W2,
                                               const float* __restrict__ av_s,
                                               const float* __restrict__ av_d) {
    __shared__ float sx[C1 * 32];   // [k][i], 32KB
    int m0 = blockIdx.x * 32;
    int tid = threadIdx.x;
    for (int idx = tid; idx < 32 * C1; idx += 256) {
        int i = idx / C1, k = idx % C1;
        sx[k * 32 + i] = (m0 + i < NN) ? g_act[(m0 + i) * C1 + k] : 0.f;
    }
    __syncthreads();
    int col = tid & 31, ir = tid >> 5;   // warp = ir, lane = col
    float acc[4] = {0.f, 0.f, 0.f, 0.f};
#pragma unroll 4
    for (int k = 0; k < C1; k++) {
        float wv = W2[k * C2 + col];
        const float4 v = *(const float4*)&sx[k * 32 + ir * 4];
        acc[0] = fmaf(v.x, wv, acc[0]);
        acc[1] = fmaf(v.y, wv, acc[1]);
        acc[2] = fmaf(v.z, wv, acc[2]);
        acc[3] = fmaf(v.w, wv, acc[3]);
    }
    float s_l = av_s[col], d_l = av_d[col];
#pragma unroll
    for (int j = 0; j < 4; j++) {
        int node = m0 + ir * 4 + j;
        if (node < NN) g_h2[node * C2 + col] = acc[j];
        float ss = acc[j] * s_l, sd = acc[j] * d_l;
#pragma unroll
        for (int o = 16; o > 0; o >>= 1) {
            ss += __shfl_down_sync(0xffffffffu, ss, o);
            sd += __shfl_down_sync(0xffffffffu, sd, o);
        }
        if (col == 0 && node < NN) { g_as2[node] = ss; g_ad2[node] = sd; }
    }
}

// ---------------- global max of g_as2 (single block) ----------------
__global__ void __launch_bounds__(1024) k_gmax2() {
    __shared__ float sr[1024];
    int t = threadIdx.x;
    float m = -1e30f;
    for (int n = t; n < NN; n += 1024) m = fmaxf(m, g_as2[n]);
    sr[t] = m;
    __syncthreads();
    for (int st = 512; st > 0; st >>= 1) {
        if (t < st) sr[t] = fmaxf(sr[t], sr[t + st]);
        __syncthreads();
    }
    if (t == 0) g_gm2[0] = sr[0];
}

// ---------------- agg2: warp per dst node, single pass, 4-way MLP ----------------
__global__ void k_agg2(const float* __restrict__ b2, float* __restrict__ out) {
    int warp = threadIdx.x >> 5;
    int n = blockIdx.x * 8 + warp;
    if (n >= NN) return;
    int lane = threadIdx.x & 31;
    int off = g_off[n], deg = g_off[n + 1] - off;
    float adn = g_ad2[n];
    float B = lrelu(g_gm2[0] + adn);   // upper bound on segment max

    float a0 = 0.f, a1 = 0.f, a2 = 0.f, a3 = 0.f;
    float w0s = 0.f, w1s = 0.f, w2s = 0.f, w3s = 0.f;
    int i = 0;
    for (; i + 3 < deg; i += 4) {
        int s0 = g_csr[off + i],     s1 = g_csr[off + i + 1];
        int s2 = g_csr[off + i + 2], s3 = g_csr[off + i + 3];
        float w0 = __expf(lrelu(g_as2[s0] + adn) - B);
        float w1 = __expf(lrelu(g_as2[s1] + adn) - B);
        float w2 = __expf(lrelu(g_as2[s2] + adn) - B);
        float w3 = __expf(lrelu(g_as2[s3] + adn) - B);
        a0 = fmaf(g_h2[s0 * C2 + lane], w0, a0);
        a1 = fmaf(g_h2[s1 * C2 + lane], w1, a1);
        a2 = fmaf(g_h2[s2 * C2 + lane], w2, a2);
        a3 = fmaf(g_h2[s3 * C2 + lane], w3, a3);
        w0s += w0; w1s += w1; w2s += w2; w3s += w3;
    }
    for (; i < deg; i++) {
        int s = g_csr[off + i];
        float w = __expf(lrelu(g_as2[s] + adn) - B);
        a0 = fmaf(g_h2[s * C2 + lane], w, a0);
        w0s += w;
    }
    out[n * C2 + lane] = (a0 + a1 + a2 + a3) / (w0s + w1s + w2s + w3s + 1e-16f) + b2[lane];
}

// ---------------- launch ----------------
extern "C" void kernel_launch(void* const* d_in, const int* in_sizes, int n_in,
                              void* d_out, int out_size) {
    const float* x    = (const float*)d_in[0];
    const int*   ei   = (const int*)d_in[1];   // int32 (JAX x64 disabled) or int64 (detected)
    const float* W1   = (const float*)d_in[2];
    const float* as1v = (const float*)d_in[3];
    const float* ad1v = (const float*)d_in[4];
    const float* b1   = (const float*)d_in[5];
    const float* W2   = (const float*)d_in[6];
    const float* as2v = (const float*)d_in[7];
    const float* ad2v = (const float*)d_in[8];
    const float* b2   = (const float*)d_in[9];
    float*       out  = (float*)d_out;

    // detect edge_index element width, then CSR build (reused by both layers)
    k_detect<<<1, 256>>>(ei);
    k_zero_deg<<<(NN + 255) / 256, 256>>>();
    k_count<<<(ETOT + 255) / 256, 256>>>(ei);
    k_scan_local<<<NB, SCAN_B>>>();
    k_scan_bsum<<<1, 128>>>();
    k_scan_add<<<NB, SCAN_B>>>();
    k_fill<<<(ETOT + 255) / 256, 256>>>(ei);

    // layer 1 (alpha fused into GEMM epilogue)
    k_gemm1<<<(NN + 31) / 32, 256>>>(x, W1, as1v, ad1v);
    k_gmax1<<<1, 1024>>>();
    k_agg1<<<NN, 128>>>(b1);

    // layer 2 (alpha fused into GEMM epilogue)
    k_gemm2<<<(NN + 31) / 32, 256>>>(W2, as2v, ad2v);
    k_gmax2<<<1, 1024>>>();
    k_agg2<<<(NN + 7) / 8, 256>>>(b2, out);
}

// round 6
// speedup vs baseline: 1.6689x; 1.1555x over previous
#include <cuda_runtime.h>
#include <cuda_bf16.h>

#define NN   50000
#define NE   800000
#define ETOT (NE + NN)   // edges + self loops
#define IN   128
#define C1   256         // HEADS*HIDDEN
#define H1   4
#define F1   64
#define C2   32
#define SCAN_B 512
#define NB   ((NN + SCAN_B - 1) / SCAN_B)   // 98

// ---------------- scratch (static device globals; no allocation) ----------------
__device__ float    g_h1 [NN * C1];
__device__ float    g_act[NN * C1];
__device__ float    g_h2 [NN * C2];
__device__ float    g_as1[NN * H1];
__device__ float    g_ad1[NN * H1];
__device__ float    g_as2[NN];
__device__ float    g_ad2[NN];
__device__ unsigned g_gm1u[4];     // encoded global per-head max of g_as1
__device__ unsigned g_gm2u;        // encoded global max of g_as2
__device__ int      g_deg[NN];
__device__ int      g_off[NN + 1];
__device__ int      g_pos[NN];
__device__ int      g_bsum[128];
__device__ int      g_boff[128];
__device__ int      g_csr[ETOT];
__device__ int      g_stride;

__device__ __forceinline__ float lrelu(float v) { return v > 0.f ? v : 0.2f * v; }

// ordered-uint encoding of float: monotone, enc range > 0 for all reals
__device__ __forceinline__ unsigned encf(float f) {
    unsigned u = __float_as_uint(f);
    return (u & 0x80000000u) ? ~u : (u | 0x80000000u);
}
__device__ __forceinline__ float decf(unsigned e) {
    return (e & 0x80000000u) ? __uint_as_float(e ^ 0x80000000u) : __uint_as_float(~e);
}

// packed fp32x2 helpers (FFMA2 — full fp32 precision, 2 lanes/instr)
__device__ __forceinline__ unsigned long long dup2(float v) {
    unsigned long long r;
    asm("mov.b64 %0, {%1, %1};" : "=l"(r) : "f"(v));
    return r;
}
__device__ __forceinline__ unsigned long long fma2(unsigned long long a,
                                                   unsigned long long b,
                                                   unsigned long long c) {
    unsigned long long d;
    asm("fma.rn.f32x2 %0, %1, %2, %3;" : "=l"(d) : "l"(a), "l"(b), "l"(c));
    return d;
}
__device__ __forceinline__ void unpack2(unsigned long long v, float& lo, float& hi) {
    asm("mov.b64 {%0, %1}, %2;" : "=f"(lo), "=f"(hi) : "l"(v));
}

// ---------------- edge_index dtype detection ----------------
__global__ void k_detect(const int* __restrict__ p) {
    __shared__ int nz[256];
    int t = threadIdx.x;
    int acc = 0;
#pragma unroll
    for (int j = 0; j < 4; j++) acc |= p[2 * (t + 256 * j) + 1];
    nz[t] = acc;
    __syncthreads();
    for (int st = 128; st > 0; st >>= 1) {
        if (t < st) nz[t] |= nz[t + st];
        __syncthreads();
    }
    if (t == 0) g_stride = (nz[0] == 0) ? 2 : 1;
}

// ---------------- CSR build ----------------
__global__ void k_zero_deg() {
    int i = blockIdx.x * blockDim.x + threadIdx.x;
    if (i < NN) g_deg[i] = 0;
    if (i < 4)  g_gm1u[i] = 0u;
    if (i == 4) g_gm2u = 0u;
}

__global__ void k_count(const int* __restrict__ ei) {
    int e = blockIdx.x * blockDim.x + threadIdx.x;
    if (e >= ETOT) return;
    int st = g_stride;
    int d = (e < NE) ? ei[(NE + e) * st] : (e - NE);
    atomicAdd(&g_deg[d], 1);
}

__global__ void k_scan_local() {
    __shared__ int s[SCAN_B];
    int i = blockIdx.x * SCAN_B + threadIdx.x;
    int v = (i < NN) ? g_deg[i] : 0;
    s[threadIdx.x] = v;
    __syncthreads();
    for (int st = 1; st < SCAN_B; st <<= 1) {
        int t = (threadIdx.x >= st) ? s[threadIdx.x - st] : 0;
        __syncthreads();
        s[threadIdx.x] += t;
        __syncthreads();
    }
    if (i < NN) g_off[i] = s[threadIdx.x] - v;
    if (threadIdx.x == SCAN_B - 1) g_bsum[blockIdx.x] = s[SCAN_B - 1];
}

__global__ void k_scan_bsum() {
    __shared__ int s[128];
    int v = (threadIdx.x < NB) ? g_bsum[threadIdx.x] : 0;
    s[threadIdx.x] = v;
    __syncthreads();
    for (int st = 1; st < 128; st <<= 1) {
        int t = (threadIdx.x >= st) ? s[threadIdx.x - st] : 0;
        __syncthreads();
        s[threadIdx.x] += t;
        __syncthreads();
    }
    if (threadIdx.x < NB) g_boff[threadIdx.x] = s[threadIdx.x] - v;
}

__global__ void k_scan_add() {
    int i = blockIdx.x * SCAN_B + threadIdx.x;
    if (i < NN) {
        int o = g_off[i] + g_boff[blockIdx.x];
        g_off[i] = o;
        g_pos[i] = o;
    }
    if (i == 0) g_off[NN] = ETOT;
}

__global__ void k_fill(const int* __restrict__ ei) {
    int e = blockIdx.x * blockDim.x + threadIdx.x;
    if (e >= ETOT) return;
    int st = g_stride;
    int s, d;
    if (e < NE) { s = ei[e * st]; d = ei[(NE + e) * st]; }
    else        { s = d = e - NE; }
    int slot = atomicAdd(&g_pos[d], 1);
    g_csr[slot] = s;
}

// ---------------- GEMM1 + alpha1 + global-max fused (FFMA2 core) ----------------
// 128 threads: thread t owns column pair (2t, 2t+1) x 32 nodes (16 node-pairs).
#define SXP 34   // padded x-tile stride (even -> 8B-aligned pairs)
__global__ void __launch_bounds__(128) k_gemm1(const float* __restrict__ x,
                                               const float* __restrict__ W1,
                                               const float* __restrict__ av_s,
                                               const float* __restrict__ av_d) {
    __shared__ float sh[32 * 256];   // 32KB; phase A: padded x tile, phase B: out tile
    __shared__ float smx[16];
    float* sx = sh;
    int m0 = blockIdx.x * 32;
    int tid = threadIdx.x;

    // x tile: sx[k*SXP + i] = x[(m0+i)*IN + k]  (coalesced global, 2-way STS)
    for (int idx = tid; idx < 32 * IN; idx += 128) {
        int i = idx >> 7, k = idx & 127;
        sx[k * SXP + i] = (m0 + i < NN) ? x[(m0 + i) * IN + k] : 0.f;
    }
    __syncthreads();

    unsigned long long accA[16], accB[16];
#pragma unroll
    for (int j = 0; j < 16; j++) { accA[j] = 0ull; accB[j] = 0ull; }

    const float2* Wp = (const float2*)W1;
#pragma unroll 2
    for (int k = 0; k < IN; k++) {
        float2 wv = Wp[k * 128 + tid];          // cols (2t, 2t+1)
        unsigned long long wlo = dup2(wv.x), whi = dup2(wv.y);
#pragma unroll
        for (int j = 0; j < 16; j++) {
            unsigned long long x2 =
                *reinterpret_cast<const unsigned long long*>(&sx[k * SXP + 2 * j]);
            accA[j] = fma2(x2, wlo, accA[j]);
            accB[j] = fma2(x2, whi, accB[j]);
        }
    }
    __syncthreads();   // all reads of sx complete

    // scatter accs into sh[node*256 + col] via conflict-free STS.64
#pragma unroll
    for (int j = 0; j < 16; j++) {
        float alo, ahi, blo, bhi;
        unpack2(accA[j], alo, ahi);
        unpack2(accB[j], blo, bhi);
        *(float2*)&sh[(2 * j)     * 256 + 2 * tid] = make_float2(alo, blo);
        *(float2*)&sh[(2 * j + 1) * 256 + 2 * tid] = make_float2(ahi, bhi);
    }
    __syncthreads();

    // coalesced store of h1
#pragma unroll
    for (int r = 0; r < 16; r++) {
        int idx = r * 128 + tid;
        int node = idx >> 6, q = idx & 63;
        if (m0 + node < NN)
            *(float4*)&g_h1[(m0 + node) * C1 + 4 * q] = *(float4*)&sh[node * 256 + 4 * q];
    }

    // alpha epilogue: warp w handles nodes w+4r (r=0..7)
    int warp = tid >> 5, lane = tid & 31;
    float a_s[8], a_d[8];
#pragma unroll
    for (int j = 0; j < 8; j++) {
        a_s[j] = av_s[lane + 32 * j];
        a_d[j] = av_d[lane + 32 * j];
    }
    float mx[4] = {-1e30f, -1e30f, -1e30f, -1e30f};
#pragma unroll
    for (int r = 0; r < 8; r++) {
        int i = warp + 4 * r;
        float ps[4] = {0.f, 0.f, 0.f, 0.f};
        float pd[4] = {0.f, 0.f, 0.f, 0.f};
#pragma unroll
        for (int j = 0; j < 8; j++) {
            float v = sh[i * 256 + lane + 32 * j];
            int h = j >> 1;
            ps[h] = fmaf(v, a_s[j], ps[h]);
            pd[h] = fmaf(v, a_d[j], pd[h]);
        }
#pragma unroll
        for (int o = 16; o > 0; o >>= 1) {
#pragma unroll
            for (int h = 0; h < 4; h++) {
                ps[h] += __shfl_down_sync(0xffffffffu, ps[h], o);
                pd[h] += __shfl_down_sync(0xffffffffu, pd[h], o);
            }
        }
        if (lane == 0 && m0 + i < NN) {
#pragma unroll
            for (int h = 0; h < 4; h++) {
                g_as1[(m0 + i) * 4 + h] = ps[h];
                g_ad1[(m0 + i) * 4 + h] = pd[h];
                mx[h] = fmaxf(mx[h], ps[h]);
            }
        }
    }
    if (lane == 0) {
#pragma unroll
        for (int h = 0; h < 4; h++) smx[warp * 4 + h] = mx[h];
    }
    __syncthreads();
    if (tid < 4) {
        float m = fmaxf(fmaxf(smx[tid], smx[4 + tid]), fmaxf(smx[8 + tid], smx[12 + tid]));
        if (m > -1e29f) atomicMax(&g_gm1u[tid], encf(m));
    }
}

// ---------------- agg1: single pass, ping-pong tiles ----------------
__global__ void __launch_bounds__(128) k_agg1(const float* __restrict__ b1) {
    int n   = blockIdx.x;
    int tid = threadIdx.x;
    int off = g_off[n];
    int deg = g_off[n + 1] - off;
    int hf  = tid >> 5;
    int i   = tid >> 2;
    int h   = tid & 3;

    __shared__ int   s_src[2][32];
    __shared__ float s_w[2][128];
    __shared__ float s4[16];

    const float4 adv = *(const float4*)&g_ad1[n * 4];
    float adh = (h == 0) ? adv.x : (h == 1) ? adv.y : (h == 2) ? adv.z : adv.w;
    float gmh = decf(g_gm1u[h]);
    float Bh  = lrelu(gmh + adh);

    float wsum = 0.f;
    float2 acc = make_float2(0.f, 0.f);

    if (i < deg) {
        int s = g_csr[off + i];
        if (h == 0) s_src[0][i] = s;
        float w = __expf(lrelu(g_as1[s * 4 + h] + adh) - Bh);
        s_w[0][(i << 2) + h] = w;
        wsum += w;
    }
    __syncthreads();

    int nt = (deg + 31) >> 5;
    for (int t = 0; t < nt; t++) {
        int cur  = t & 1;
        int base = t << 5;
        int cnt  = min(32, deg - base);
        int nb   = base + 32;
        if (nb + i < deg) {
            int s = g_csr[off + nb + i];
            if (h == 0) s_src[cur ^ 1][i] = s;
            float w = __expf(lrelu(g_as1[s * 4 + h] + adh) - Bh);
            s_w[cur ^ 1][(i << 2) + h] = w;
            wsum += w;
        }
#pragma unroll 4
        for (int j = 0; j < cnt; j++) {
            float2 v = ((const float2*)&g_h1[s_src[cur][j] * C1])[tid];
            float  w = s_w[cur][(j << 2) + hf];
            acc.x = fmaf(v.x, w, acc.x);
            acc.y = fmaf(v.y, w, acc.y);
        }
        __syncthreads();
    }

    wsum += __shfl_xor_sync(0xffffffffu, wsum, 16);
    wsum += __shfl_xor_sync(0xffffffffu, wsum, 8);
    wsum += __shfl_xor_sync(0xffffffffu, wsum, 4);
    int lane = tid & 31, warp = tid >> 5;
    if (lane < 4) s4[warp * 4 + lane] = wsum;
    __syncthreads();
    float denom = s4[hf] + s4[4 + hf] + s4[8 + hf] + s4[12 + hf] + 1e-16f;

    float2 bb = ((const float2*)b1)[tid];
    float ox = acc.x / denom + bb.x;
    float oy = acc.y / denom + bb.y;
    ox = (ox > 0.f) ? ox : expm1f(ox);
    oy = (oy > 0.f) ? oy : expm1f(oy);
    ((float2*)&g_act[n * C1])[tid] = make_float2(ox, oy);
}

// ---------------- GEMM2 + alpha2 + global-max fused (FFMA2 core) ----------------
__global__ void __launch_bounds__(256) k_gemm2(const float* __restrict__ W2,
                                               const float* __restrict__ av_s,
                                               const float* __restrict__ av_d) {
    __shared__ float sx[C1 * 32];
    __shared__ float sm8[8];
    int m0 = blockIdx.x * 32;
    int tid = threadIdx.x;
    for (int idx = tid; idx < 32 * C1; idx += 256) {
        int i = idx / C1, k = idx % C1;
        sx[k * 32 + i] = (m0 + i < NN) ? g_act[(m0 + i) * C1 + k] : 0.f;
    }
    __syncthreads();
    int col = tid & 31, ir = tid >> 5;
    unsigned long long acc01 = 0ull, acc23 = 0ull;
#pragma unroll 4
    for (int k = 0; k < C1; k++) {
        unsigned long long wd = dup2(W2[k * C2 + col]);
        unsigned long long x01 =
            *reinterpret_cast<const unsigned long long*>(&sx[k * 32 + ir * 4]);
        unsigned long long x23 =
            *reinterpret_cast<const unsigned long long*>(&sx[k * 32 + ir * 4 + 2]);
        acc01 = fma2(x01, wd, acc01);
        acc23 = fma2(x23, wd, acc23);
    }
    float acc[4];
    unpack2(acc01, acc[0], acc[1]);
    unpack2(acc23, acc[2], acc[3]);

    float s_l = av_s[col], d_l = av_d[col];
    float mx = -1e30f;
#pragma unroll
    for (int j = 0; j < 4; j++) {
        int node = m0 + ir * 4 + j;
        if (node < NN) g_h2[node * C2 + col] = acc[j];
        float ss = acc[j] * s_l, sd = acc[j] * d_l;
#pragma unroll
        for (int o = 16; o > 0; o >>= 1) {
            ss += __shfl_down_sync(0xffffffffu, ss, o);
            sd += __shfl_down_sync(0xffffffffu, sd, o);
        }
        if (col == 0 && node < NN) {
            g_as2[node] = ss;
            g_ad2[node] = sd;
            mx = fmaxf(mx, ss);
        }
    }
    if (col == 0) sm8[ir] = mx;
    __syncthreads();
    if (tid == 0) {
        float m = -1e30f;
#pragma unroll
        for (int w = 0; w < 8; w++) m = fmaxf(m, sm8[w]);
        if (m > -1e29f) atomicMax(&g_gm2u, encf(m));
    }
}

// ---------------- agg2: warp per dst node, single pass, 4-way MLP ----------------
__global__ void k_agg2(const float* __restrict__ b2, float* __restrict__ out) {
    int warp = threadIdx.x >> 5;
    int n = blockIdx.x * 8 + warp;
    if (n >= NN) return;
    int lane = threadIdx.x & 31;
    int off = g_off[n], deg = g_off[n + 1] - off;
    float adn = g_ad2[n];
    float B = lrelu(decf(g_gm2u) + adn);

    float a0 = 0.f, a1 = 0.f, a2 = 0.f, a3 = 0.f;
    float w0s = 0.f, w1s = 0.f, w2s = 0.f, w3s = 0.f;
    int i = 0;
    for (; i + 3 < deg; i += 4) {
        int s0 = g_csr[off + i],     s1 = g_csr[off + i + 1];
        int s2 = g_csr[off + i + 2], s3 = g_csr[off + i + 3];
        float w0 = __expf(lrelu(g_as2[s0] + adn) - B);
        float w1 = __expf(lrelu(g_as2[s1] + adn) - B);
        float w2 = __expf(lrelu(g_as2[s2] + adn) - B);
        float w3 = __expf(lrelu(g_as2[s3] + adn) - B);
        a0 = fmaf(g_h2[s0 * C2 + lane], w0, a0);
        a1 = fmaf(g_h2[s1 * C2 + lane], w1, a1);
        a2 = fmaf(g_h2[s2 * C2 + lane], w2, a2);
        a3 = fmaf(g_h2[s3 * C2 + lane], w3, a3);
        w0s += w0; w1s += w1; w2s += w2; w3s += w3;
    }
    for (; i < deg; i++) {
        int s = g_csr[off + i];
        float w = __expf(lrelu(g_as2[s] + adn) - B);
        a0 = fmaf(g_h2[s * C2 + lane], w, a0);
        w0s += w;
    }
    out[n * C2 + lane] = (a0 + a1 + a2 + a3) / (w0s + w1s + w2s + w3s + 1e-16f) + b2[lane];
}

// ---------------- launch ----------------
extern "C" void kernel_launch(void* const* d_in, const int* in_sizes, int n_in,
                              void* d_out, int out_size) {
    const float* x    = (const float*)d_in[0];
    const int*   ei   = (const int*)d_in[1];
    const float* W1   = (const float*)d_in[2];
    const float* as1v = (const float*)d_in[3];
    const float* ad1v = (const float*)d_in[4];
    const float* b1   = (const float*)d_in[5];
    const float* W2   = (const float*)d_in[6];
    const float* as2v = (const float*)d_in[7];
    const float* ad2v = (const float*)d_in[8];
    const float* b2   = (const float*)d_in[9];
    float*       out  = (float*)d_out;

    k_detect<<<1, 256>>>(ei);
    k_zero_deg<<<(NN + 255) / 256, 256>>>();
    k_count<<<(ETOT + 255) / 256, 256>>>(ei);
    k_scan_local<<<NB, SCAN_B>>>();
    k_scan_bsum<<<1, 128>>>();
    k_scan_add<<<NB, SCAN_B>>>();
    k_fill<<<(ETOT + 255) / 256, 256>>>(ei);

    k_gemm1<<<(NN + 31) / 32, 128>>>(x, W1, as1v, ad1v);
    k_agg1<<<NN, 128>>>(b1);

    k_gemm2<<<(NN + 31) / 32, 256>>>(W2, as2v, ad2v);
    k_agg2<<<(NN + 7) / 8, 256>>>(b2, out);
}

// round 7
// speedup vs baseline: 1.6735x; 1.0027x over previous
#include <cuda_runtime.h>
#include <cuda_bf16.h>

#define NN   50000
#define NE   800000
#define ETOT (NE + NN)   // edges + self loops
#define IN   128
#define C1   256         // HEADS*HIDDEN
#define H1   4
#define F1   64
#define C2   32
#define SCAN_B 512
#define NB   ((NN + SCAN_B - 1) / SCAN_B)   // 98

// ---------------- scratch (static device globals; no allocation) ----------------
__device__ float    g_h1 [NN * C1];
__device__ float    g_act[NN * C1];
__device__ float    g_h2 [NN * C2];
__device__ float    g_as1[NN * H1];
__device__ float    g_ad1[NN * H1];
__device__ float    g_as2[NN];
__device__ float    g_ad2[NN];
__device__ float    g_w   [ETOT * 4];  // per-edge per-head softmax numerators
__device__ float    g_wsum[NN * 4];    // per-node per-head denominators
__device__ unsigned g_gm1u[4];
__device__ unsigned g_gm2u;
__device__ int      g_deg[NN];
__device__ int      g_off[NN + 1];
__device__ int      g_pos[NN];
__device__ int      g_bsum[128];
__device__ int      g_boff[128];
__device__ int      g_csr[ETOT];
__device__ int      g_stride;

__device__ __forceinline__ float lrelu(float v) { return v > 0.f ? v : 0.2f * v; }

__device__ __forceinline__ unsigned encf(float f) {
    unsigned u = __float_as_uint(f);
    return (u & 0x80000000u) ? ~u : (u | 0x80000000u);
}
__device__ __forceinline__ float decf(unsigned e) {
    return (e & 0x80000000u) ? __uint_as_float(e ^ 0x80000000u) : __uint_as_float(~e);
}

// packed fp32x2 helpers (FFMA2 — full fp32 precision, 2 lanes/instr)
__device__ __forceinline__ unsigned long long dup2(float v) {
    unsigned long long r;
    asm("mov.b64 %0, {%1, %1};" : "=l"(r) : "f"(v));
    return r;
}
__device__ __forceinline__ unsigned long long fma2(unsigned long long a,
                                                   unsigned long long b,
                                                   unsigned long long c) {
    unsigned long long d;
    asm("fma.rn.f32x2 %0, %1, %2, %3;" : "=l"(d) : "l"(a), "l"(b), "l"(c));
    return d;
}
__device__ __forceinline__ void unpack2(unsigned long long v, float& lo, float& hi) {
    asm("mov.b64 {%0, %1}, %2;" : "=f"(lo), "=f"(hi) : "l"(v));
}

// ---------------- zero + edge_index dtype detection (block 0) ----------------
__global__ void k_zero_deg(const int* __restrict__ p) {
    int i = blockIdx.x * blockDim.x + threadIdx.x;
    if (i < NN) g_deg[i] = 0;
    if (i < 4)  g_gm1u[i] = 0u;
    if (i == 4) g_gm2u = 0u;
    if (blockIdx.x == 0) {
        __shared__ int nz[256];
        int t = threadIdx.x;
        int acc = 0;
#pragma unroll
        for (int j = 0; j < 4; j++) acc |= p[2 * (t + 256 * j) + 1];
        nz[t] = acc;
        __syncthreads();
        for (int st = 128; st > 0; st >>= 1) {
            if (t < st) nz[t] |= nz[t + st];
            __syncthreads();
        }
        if (t == 0) g_stride = (nz[0] == 0) ? 2 : 1;
    }
}

// ---------------- CSR build ----------------
__global__ void k_count(const int* __restrict__ ei) {
    int e = blockIdx.x * blockDim.x + threadIdx.x;
    if (e >= ETOT) return;
    int st = g_stride;
    int d = (e < NE) ? ei[(NE + e) * st] : (e - NE);
    atomicAdd(&g_deg[d], 1);
}

__global__ void k_scan_local() {
    __shared__ int s[SCAN_B];
    int i = blockIdx.x * SCAN_B + threadIdx.x;
    int v = (i < NN) ? g_deg[i] : 0;
    s[threadIdx.x] = v;
    __syncthreads();
    for (int st = 1; st < SCAN_B; st <<= 1) {
        int t = (threadIdx.x >= st) ? s[threadIdx.x - st] : 0;
        __syncthreads();
        s[threadIdx.x] += t;
        __syncthreads();
    }
    if (i < NN) g_off[i] = s[threadIdx.x] - v;
    if (threadIdx.x == SCAN_B - 1) g_bsum[blockIdx.x] = s[SCAN_B - 1];
}

__global__ void k_scan_bsum() {
    __shared__ int s[128];
    int v = (threadIdx.x < NB) ? g_bsum[threadIdx.x] : 0;
    s[threadIdx.x] = v;
    __syncthreads();
    for (int st = 1; st < 128; st <<= 1) {
        int t = (threadIdx.x >= st) ? s[threadIdx.x - st] : 0;
        __syncthreads();
        s[threadIdx.x] += t;
        __syncthreads();
    }
    if (threadIdx.x < NB) g_boff[threadIdx.x] = s[threadIdx.x] - v;
}

__global__ void k_scan_add() {
    int i = blockIdx.x * SCAN_B + threadIdx.x;
    if (i < NN) {
        int o = g_off[i] + g_boff[blockIdx.x];
        g_off[i] = o;
        g_pos[i] = o;
    }
    if (i == 0) g_off[NN] = ETOT;
}

__global__ void k_fill(const int* __restrict__ ei) {
    int e = blockIdx.x * blockDim.x + threadIdx.x;
    if (e >= ETOT) return;
    int st = g_stride;
    int s, d;
    if (e < NE) { s = ei[e * st]; d = ei[(NE + e) * st]; }
    else        { s = d = e - NE; }
    int slot = atomicAdd(&g_pos[d], 1);
    g_csr[slot] = s;
}

// ---------------- GEMM1 + alpha1 + global-max fused (FFMA2 core) ----------------
#define SXP 34
__global__ void __launch_bounds__(128) k_gemm1(const float* __restrict__ x,
                                               const float* __restrict__ W1,
                                               const float* __restrict__ av_s,
                                               const float* __restrict__ av_d) {
    __shared__ float sh[32 * 256];   // 32KB; phase A: padded x tile, phase B: out tile
    __shared__ float smx[16];
    float* sx = sh;
    int m0 = blockIdx.x * 32;
    int tid = threadIdx.x;

    for (int idx = tid; idx < 32 * IN; idx += 128) {
        int i = idx >> 7, k = idx & 127;
        sx[k * SXP + i] = (m0 + i < NN) ? x[(m0 + i) * IN + k] : 0.f;
    }
    __syncthreads();

    unsigned long long accA[16], accB[16];
#pragma unroll
    for (int j = 0; j < 16; j++) { accA[j] = 0ull; accB[j] = 0ull; }

    const float2* Wp = (const float2*)W1;
#pragma unroll 2
    for (int k = 0; k < IN; k++) {
        float2 wv = Wp[k * 128 + tid];
        unsigned long long wlo = dup2(wv.x), whi = dup2(wv.y);
#pragma unroll
        for (int j = 0; j < 16; j++) {
            unsigned long long x2 =
                *reinterpret_cast<const unsigned long long*>(&sx[k * SXP + 2 * j]);
            accA[j] = fma2(x2, wlo, accA[j]);
            accB[j] = fma2(x2, whi, accB[j]);
        }
    }
    __syncthreads();

#pragma unroll
    for (int j = 0; j < 16; j++) {
        float alo, ahi, blo, bhi;
        unpack2(accA[j], alo, ahi);
        unpack2(accB[j], blo, bhi);
        *(float2*)&sh[(2 * j)     * 256 + 2 * tid] = make_float2(alo, blo);
        *(float2*)&sh[(2 * j + 1) * 256 + 2 * tid] = make_float2(ahi, bhi);
    }
    __syncthreads();

#pragma unroll
    for (int r = 0; r < 16; r++) {
        int idx = r * 128 + tid;
        int node = idx >> 6, q = idx & 63;
        if (m0 + node < NN)
            *(float4*)&g_h1[(m0 + node) * C1 + 4 * q] = *(float4*)&sh[node * 256 + 4 * q];
    }

    int warp = tid >> 5, lane = tid & 31;
    float a_s[8], a_d[8];
#pragma unroll
    for (int j = 0; j < 8; j++) {
        a_s[j] = av_s[lane + 32 * j];
        a_d[j] = av_d[lane + 32 * j];
    }
    float mx[4] = {-1e30f, -1e30f, -1e30f, -1e30f};
#pragma unroll
    for (int r = 0; r < 8; r++) {
        int i = warp + 4 * r;
        float ps[4] = {0.f, 0.f, 0.f, 0.f};
        float pd[4] = {0.f, 0.f, 0.f, 0.f};
#pragma unroll
        for (int j = 0; j < 8; j++) {
            float v = sh[i * 256 + lane + 32 * j];
            int h = j >> 1;
            ps[h] = fmaf(v, a_s[j], ps[h]);
            pd[h] = fmaf(v, a_d[j], pd[h]);
        }
#pragma unroll
        for (int o = 16; o > 0; o >>= 1) {
#pragma unroll
            for (int h = 0; h < 4; h++) {
                ps[h] += __shfl_down_sync(0xffffffffu, ps[h], o);
                pd[h] += __shfl_down_sync(0xffffffffu, pd[h], o);
            }
        }
        if (lane == 0 && m0 + i < NN) {
#pragma unroll
            for (int h = 0; h < 4; h++) {
                g_as1[(m0 + i) * 4 + h] = ps[h];
                g_ad1[(m0 + i) * 4 + h] = pd[h];
                mx[h] = fmaxf(mx[h], ps[h]);
            }
        }
    }
    if (lane == 0) {
#pragma unroll
        for (int h = 0; h < 4; h++) smx[warp * 4 + h] = mx[h];
    }
    __syncthreads();
    if (tid < 4) {
        float m = fmaxf(fmaxf(smx[tid], smx[4 + tid]), fmaxf(smx[8 + tid], smx[12 + tid]));
        if (m > -1e29f) atomicMax(&g_gm1u[tid], encf(m));
    }
}

// ---------------- k_wts: per-edge softmax weights + per-node sums (warp/node) ----------------
__global__ void k_wts() {
    int warp = threadIdx.x >> 5;
    int n = blockIdx.x * 8 + warp;
    if (n >= NN) return;
    int lane = threadIdx.x & 31;
    int off = g_off[n], deg = g_off[n + 1] - off;

    const float4 adv = *(const float4*)&g_ad1[n * 4];
    float B0 = lrelu(decf(g_gm1u[0]) + adv.x);
    float B1 = lrelu(decf(g_gm1u[1]) + adv.y);
    float B2 = lrelu(decf(g_gm1u[2]) + adv.z);
    float B3 = lrelu(decf(g_gm1u[3]) + adv.w);

    float4 ws = make_float4(0.f, 0.f, 0.f, 0.f);
    for (int i = lane; i < deg; i += 32) {
        int s = g_csr[off + i];
        const float4 av = *(const float4*)&g_as1[s * 4];
        float w0 = __expf(lrelu(av.x + adv.x) - B0);
        float w1 = __expf(lrelu(av.y + adv.y) - B1);
        float w2 = __expf(lrelu(av.z + adv.z) - B2);
        float w3 = __expf(lrelu(av.w + adv.w) - B3);
        *(float4*)&g_w[(off + i) * 4] = make_float4(w0, w1, w2, w3);
        ws.x += w0; ws.y += w1; ws.z += w2; ws.w += w3;
    }
#pragma unroll
    for (int o = 16; o > 0; o >>= 1) {
        ws.x += __shfl_xor_sync(0xffffffffu, ws.x, o);
        ws.y += __shfl_xor_sync(0xffffffffu, ws.y, o);
        ws.z += __shfl_xor_sync(0xffffffffu, ws.z, o);
        ws.w += __shfl_xor_sync(0xffffffffu, ws.w, o);
    }
    if (lane == 0) *(float4*)&g_wsum[n * 4] = ws;
}

// ---------------- agg1: pure streaming gather — no smem, no barriers ----------------
__global__ void __launch_bounds__(128) k_agg1(const float* __restrict__ b1) {
    int n   = blockIdx.x;
    int tid = threadIdx.x;
    int off = g_off[n];
    int deg = g_off[n + 1] - off;
    int hf  = tid >> 5;          // head of this feature pair

    unsigned long long acc = 0ull, acc2 = 0ull;
    int j = 0;
    for (; j + 3 < deg; j += 4) {
        int s0 = g_csr[off + j],     s1 = g_csr[off + j + 1];
        int s2 = g_csr[off + j + 2], s3 = g_csr[off + j + 3];
        float w0 = g_w[(off + j) * 4 + hf];
        float w1 = g_w[(off + j + 1) * 4 + hf];
        float w2 = g_w[(off + j + 2) * 4 + hf];
        float w3 = g_w[(off + j + 3) * 4 + hf];
        unsigned long long v0 = ((const unsigned long long*)&g_h1[s0 * C1])[tid];
        unsigned long long v1 = ((const unsigned long long*)&g_h1[s1 * C1])[tid];
        unsigned long long v2 = ((const unsigned long long*)&g_h1[s2 * C1])[tid];
        unsigned long long v3 = ((const unsigned long long*)&g_h1[s3 * C1])[tid];
        acc  = fma2(v0, dup2(w0), acc);
        acc2 = fma2(v1, dup2(w1), acc2);
        acc  = fma2(v2, dup2(w2), acc);
        acc2 = fma2(v3, dup2(w3), acc2);
    }
    for (; j < deg; j++) {
        int s = g_csr[off + j];
        float w = g_w[(off + j) * 4 + hf];
        unsigned long long v = ((const unsigned long long*)&g_h1[s * C1])[tid];
        acc = fma2(v, dup2(w), acc);
    }
    float ax, ay, bx, by;
    unpack2(acc, ax, ay);
    unpack2(acc2, bx, by);
    float denom = g_wsum[n * 4 + hf] + 1e-16f;

    float2 bb = ((const float2*)b1)[tid];
    float ox = (ax + bx) / denom + bb.x;
    float oy = (ay + by) / denom + bb.y;
    ox = (ox > 0.f) ? ox : expm1f(ox);
    oy = (oy > 0.f) ? oy : expm1f(oy);
    ((float2*)&g_act[n * C1])[tid] = make_float2(ox, oy);
}

// ---------------- GEMM2 + alpha2 + global-max fused (FFMA2 core) ----------------
__global__ void __launch_bounds__(256) k_gemm2(const float* __restrict__ W2,
                                               const float* __restrict__ av_s,
                                               const float* __restrict__ av_d) {
    __shared__ float sx[C1 * 32];
    __shared__ float sm8[8];
    int m0 = blockIdx.x * 32;
    int tid = threadIdx.x;
    for (int idx = tid; idx < 32 * C1; idx += 256) {
        int i = idx / C1, k = idx % C1;
        sx[k * 32 + i] = (m0 + i < NN) ? g_act[(m0 + i) * C1 + k] : 0.f;
    }
    __syncthreads();
    int col = tid & 31, ir = tid >> 5;
    unsigned long long acc01 = 0ull, acc23 = 0ull;
#pragma unroll 4
    for (int k = 0; k < C1; k++) {
        unsigned long long wd = dup2(W2[k * C2 + col]);
        unsigned long long x01 =
            *reinterpret_cast<const unsigned long long*>(&sx[k * 32 + ir * 4]);
        unsigned long long x23 =
            *reinterpret_cast<const unsigned long long*>(&sx[k * 32 + ir * 4 + 2]);
        acc01 = fma2(x01, wd, acc01);
        acc23 = fma2(x23, wd, acc23);
    }
    float acc[4];
    unpack2(acc01, acc[0], acc[1]);
    unpack2(acc23, acc[2], acc[3]);

    float s_l = av_s[col], d_l = av_d[col];
    float mx = -1e30f;
#pragma unroll
    for (int j = 0; j < 4; j++) {
        int node = m0 + ir * 4 + j;
        if (node < NN) g_h2[node * C2 + col] = acc[j];
        float ss = acc[j] * s_l, sd = acc[j] * d_l;
#pragma unroll
        for (int o = 16; o > 0; o >>= 1) {
            ss += __shfl_down_sync(0xffffffffu, ss, o);
            sd += __shfl_down_sync(0xffffffffu, sd, o);
        }
        if (col == 0 && node < NN) {
            g_as2[node] = ss;
            g_ad2[node] = sd;
            mx = fmaxf(mx, ss);
        }
    }
    if (col == 0) sm8[ir] = mx;
    __syncthreads();
    if (tid == 0) {
        float m = -1e30f;
#pragma unroll
        for (int w = 0; w < 8; w++) m = fmaxf(m, sm8[w]);
        if (m > -1e29f) atomicMax(&g_gm2u, encf(m));
    }
}

// ---------------- agg2: warp per dst node, single pass, 4-way MLP ----------------
__global__ void k_agg2(const float* __restrict__ b2, float* __restrict__ out) {
    int warp = threadIdx.x >> 5;
    int n = blockIdx.x * 8 + warp;
    if (n >= NN) return;
    int lane = threadIdx.x & 31;
    int off = g_off[n], deg = g_off[n + 1] - off;
    float adn = g_ad2[n];
    float B = lrelu(decf(g_gm2u) + adn);

    float a0 = 0.f, a1 = 0.f, a2 = 0.f, a3 = 0.f;
    float w0s = 0.f, w1s = 0.f, w2s = 0.f, w3s = 0.f;
    int i = 0;
    for (; i + 3 < deg; i += 4) {
        int s0 = g_csr[off + i],     s1 = g_csr[off + i + 1];
        int s2 = g_csr[off + i + 2], s3 = g_csr[off + i + 3];
        float w0 = __expf(lrelu(g_as2[s0] + adn) - B);
        float w1 = __expf(lrelu(g_as2[s1] + adn) - B);
        float w2 = __expf(lrelu(g_as2[s2] + adn) - B);
        float w3 = __expf(lrelu(g_as2[s3] + adn) - B);
        a0 = fmaf(g_h2[s0 * C2 + lane], w0, a0);
        a1 = fmaf(g_h2[s1 * C2 + lane], w1, a1);
        a2 = fmaf(g_h2[s2 * C2 + lane], w2, a2);
        a3 = fmaf(g_h2[s3 * C2 + lane], w3, a3);
        w0s += w0; w1s += w1; w2s += w2; w3s += w3;
    }
    for (; i < deg; i++) {
        int s = g_csr[off + i];
        float w = __expf(lrelu(g_as2[s] + adn) - B);
        a0 = fmaf(g_h2[s * C2 + lane], w, a0);
        w0s += w;
    }
    out[n * C2 + lane] = (a0 + a1 + a2 + a3) / (w0s + w1s + w2s + w3s + 1e-16f) + b2[lane];
}

// ---------------- launch ----------------
extern "C" void kernel_launch(void* const* d_in, const int* in_sizes, int n_in,
                              void* d_out, int out_size) {
    const float* x    = (const float*)d_in[0];
    const int*   ei   = (const int*)d_in[1];
    const float* W1   = (const float*)d_in[2];
    const float* as1v = (const float*)d_in[3];
    const float* ad1v = (const float*)d_in[4];
    const float* b1   = (const float*)d_in[5];
    const float* W2   = (const float*)d_in[6];
    const float* as2v = (const float*)d_in[7];
    const float* ad2v = (const float*)d_in[8];
    const float* b2   = (const float*)d_in[9];
    float*       out  = (float*)d_out;

    k_zero_deg<<<(NN + 255) / 256, 256>>>(ei);   // also detects edge dtype
    k_count<<<(ETOT + 255) / 256, 256>>>(ei);
    k_scan_local<<<NB, SCAN_B>>>();
    k_scan_bsum<<<1, 128>>>();
    k_scan_add<<<NB, SCAN_B>>>();
    k_fill<<<(ETOT + 255) / 256, 256>>>(ei);

    k_gemm1<<<(NN + 31) / 32, 128>>>(x, W1, as1v, ad1v);
    k_wts<<<(NN + 7) / 8, 256>>>();
    k_agg1<<<NN, 128>>>(b1);

    k_gemm2<<<(NN + 31) / 32, 256>>>(W2, as2v, ad2v);
    k_agg2<<<(NN + 7) / 8, 256>>>(b2, out);
}

// round 8
// speedup vs baseline: 1.7362x; 1.0375x over previous
#include <cuda_runtime.h>
#include <cuda_bf16.h>

#define NN   50000
#define NE   800000
#define ETOT (NE + NN)   // edges + self loops
#define IN   128
#define C1   256         // HEADS*HIDDEN
#define H1   4
#define F1   64
#define C2   32
#define SCAN_B 512
#define NB   ((NN + SCAN_B - 1) / SCAN_B)   // 98

// ---------------- scratch (static device globals; no allocation) ----------------
__device__ float    g_h1 [NN * C1];
__device__ float    g_act[NN * C1];
__device__ float    g_h2 [NN * C2];
__device__ float    g_as1[NN * H1];
__device__ float    g_ad1[NN * H1];
__device__ float    g_as2[NN];
__device__ float    g_ad2[NN];
__device__ float    g_w   [ETOT * 4];  // per-edge per-head softmax numerators
__device__ float    g_wsum[NN * 4];    // per-node per-head denominators
__device__ unsigned g_gm1u[4];
__device__ unsigned g_gm2u;
__device__ int      g_deg[NN];
__device__ int      g_off[NN + 1];
__device__ int      g_pos[NN];
__device__ int      g_bsum[128];
__device__ int      g_boff[128];
__device__ int      g_csr[ETOT];
__device__ int      g_stride;

__device__ __forceinline__ float lrelu(float v) { return v > 0.f ? v : 0.2f * v; }

__device__ __forceinline__ unsigned encf(float f) {
    unsigned u = __float_as_uint(f);
    return (u & 0x80000000u) ? ~u : (u | 0x80000000u);
}
__device__ __forceinline__ float decf(unsigned e) {
    return (e & 0x80000000u) ? __uint_as_float(e ^ 0x80000000u) : __uint_as_float(~e);
}

// packed fp32x2 helpers (FFMA2 — full fp32 precision, 2 lanes/instr)
__device__ __forceinline__ unsigned long long dup2(float v) {
    unsigned long long r;
    asm("mov.b64 %0, {%1, %1};" : "=l"(r) : "f"(v));
    return r;
}
__device__ __forceinline__ unsigned long long fma2(unsigned long long a,
                                                   unsigned long long b,
                                                   unsigned long long c) {
    unsigned long long d;
    asm("fma.rn.f32x2 %0, %1, %2, %3;" : "=l"(d) : "l"(a), "l"(b), "l"(c));
    return d;
}
__device__ __forceinline__ void unpack2(unsigned long long v, float& lo, float& hi) {
    asm("mov.b64 {%0, %1}, %2;" : "=f"(lo), "=f"(hi) : "l"(v));
}

// ---------------- zero + edge_index dtype detection (block 0) ----------------
__global__ void k_zero_deg(const int* __restrict__ p) {
    int i = blockIdx.x * blockDim.x + threadIdx.x;
    if (i < NN) g_deg[i] = 0;
    if (i < 4)  g_gm1u[i] = 0u;
    if (i == 4) g_gm2u = 0u;
    if (blockIdx.x == 0) {
        __shared__ int nz[256];
        int t = threadIdx.x;
        int acc = 0;
#pragma unroll
        for (int j = 0; j < 4; j++) acc |= p[2 * (t + 256 * j) + 1];
        nz[t] = acc;
        __syncthreads();
        for (int st = 128; st > 0; st >>= 1) {
            if (t < st) nz[t] |= nz[t + st];
            __syncthreads();
        }
        if (t == 0) g_stride = (nz[0] == 0) ? 2 : 1;
    }
}

// ---------------- CSR build ----------------
__global__ void k_count(const int* __restrict__ ei) {
    int e = blockIdx.x * blockDim.x + threadIdx.x;
    if (e >= ETOT) return;
    int st = g_stride;
    int d = (e < NE) ? ei[(NE + e) * st] : (e - NE);
    atomicAdd(&g_deg[d], 1);
}

__global__ void k_scan_local() {
    __shared__ int s[SCAN_B];
    int i = blockIdx.x * SCAN_B + threadIdx.x;
    int v = (i < NN) ? g_deg[i] : 0;
    s[threadIdx.x] = v;
    __syncthreads();
    for (int st = 1; st < SCAN_B; st <<= 1) {
        int t = (threadIdx.x >= st) ? s[threadIdx.x - st] : 0;
        __syncthreads();
        s[threadIdx.x] += t;
        __syncthreads();
    }
    if (i < NN) g_off[i] = s[threadIdx.x] - v;
    if (threadIdx.x == SCAN_B - 1) g_bsum[blockIdx.x] = s[SCAN_B - 1];
}

__global__ void k_scan_bsum() {
    __shared__ int s[128];
    int v = (threadIdx.x < NB) ? g_bsum[threadIdx.x] : 0;
    s[threadIdx.x] = v;
    __syncthreads();
    for (int st = 1; st < 128; st <<= 1) {
        int t = (threadIdx.x >= st) ? s[threadIdx.x - st] : 0;
        __syncthreads();
        s[threadIdx.x] += t;
        __syncthreads();
    }
    if (threadIdx.x < NB) g_boff[threadIdx.x] = s[threadIdx.x] - v;
}

__global__ void k_scan_add() {
    int i = blockIdx.x * SCAN_B + threadIdx.x;
    if (i < NN) {
        int o = g_off[i] + g_boff[blockIdx.x];
        g_off[i] = o;
        g_pos[i] = o;
    }
    if (i == 0) g_off[NN] = ETOT;
}

__global__ void k_fill(const int* __restrict__ ei) {
    int e = blockIdx.x * blockDim.x + threadIdx.x;
    if (e >= ETOT) return;
    int st = g_stride;
    int s, d;
    if (e < NE) { s = ei[e * st]; d = ei[(NE + e) * st]; }
    else        { s = d = e - NE; }
    int slot = atomicAdd(&g_pos[d], 1);
    g_csr[slot] = s;
}

// ---------------- GEMM1 + alpha1 + global-max fused (FFMA2 core) ----------------
#define SXP 34
__global__ void __launch_bounds__(128) k_gemm1(const float* __restrict__ x,
                                               const float* __restrict__ W1,
                                               const float* __restrict__ av_s,
                                               const float* __restrict__ av_d) {
    __shared__ float sh[32 * 256];   // 32KB; phase A: padded x tile, phase B: out tile
    __shared__ float smx[16];
    float* sx = sh;
    int m0 = blockIdx.x * 32;
    int tid = threadIdx.x;

    for (int idx = tid; idx < 32 * IN; idx += 128) {
        int i = idx >> 7, k = idx & 127;
        sx[k * SXP + i] = (m0 + i < NN) ? x[(m0 + i) * IN + k] : 0.f;
    }
    __syncthreads();

    unsigned long long accA[16], accB[16];
#pragma unroll
    for (int j = 0; j < 16; j++) { accA[j] = 0ull; accB[j] = 0ull; }

    const float2* Wp = (const float2*)W1;
#pragma unroll 2
    for (int k = 0; k < IN; k++) {
        float2 wv = Wp[k * 128 + tid];
        unsigned long long wlo = dup2(wv.x), whi = dup2(wv.y);
#pragma unroll
        for (int j = 0; j < 16; j++) {
            unsigned long long x2 =
                *reinterpret_cast<const unsigned long long*>(&sx[k * SXP + 2 * j]);
            accA[j] = fma2(x2, wlo, accA[j]);
            accB[j] = fma2(x2, whi, accB[j]);
        }
    }
    __syncthreads();

#pragma unroll
    for (int j = 0; j < 16; j++) {
        float alo, ahi, blo, bhi;
        unpack2(accA[j], alo, ahi);
        unpack2(accB[j], blo, bhi);
        *(float2*)&sh[(2 * j)     * 256 + 2 * tid] = make_float2(alo, blo);
        *(float2*)&sh[(2 * j + 1) * 256 + 2 * tid] = make_float2(ahi, bhi);
    }
    __syncthreads();

#pragma unroll
    for (int r = 0; r < 16; r++) {
        int idx = r * 128 + tid;
        int node = idx >> 6, q = idx & 63;
        if (m0 + node < NN)
            *(float4*)&g_h1[(m0 + node) * C1 + 4 * q] = *(float4*)&sh[node * 256 + 4 * q];
    }

    int warp = tid >> 5, lane = tid & 31;
    float a_s[8], a_d[8];
#pragma unroll
    for (int j = 0; j < 8; j++) {
        a_s[j] = av_s[lane + 32 * j];
        a_d[j] = av_d[lane + 32 * j];
    }
    float mx[4] = {-1e30f, -1e30f, -1e30f, -1e30f};
#pragma unroll
    for (int r = 0; r < 8; r++) {
        int i = warp + 4 * r;
        float ps[4] = {0.f, 0.f, 0.f, 0.f};
        float pd[4] = {0.f, 0.f, 0.f, 0.f};
#pragma unroll
        for (int j = 0; j < 8; j++) {
            float v = sh[i * 256 + lane + 32 * j];
            int h = j >> 1;
            ps[h] = fmaf(v, a_s[j], ps[h]);
            pd[h] = fmaf(v, a_d[j], pd[h]);
        }
#pragma unroll
        for (int o = 16; o > 0; o >>= 1) {
#pragma unroll
            for (int h = 0; h < 4; h++) {
                ps[h] += __shfl_down_sync(0xffffffffu, ps[h], o);
                pd[h] += __shfl_down_sync(0xffffffffu, pd[h], o);
            }
        }
        if (lane == 0 && m0 + i < NN) {
#pragma unroll
            for (int h = 0; h < 4; h++) {
                g_as1[(m0 + i) * 4 + h] = ps[h];
                g_ad1[(m0 + i) * 4 + h] = pd[h];
                mx[h] = fmaxf(mx[h], ps[h]);
            }
        }
    }
    if (lane == 0) {
#pragma unroll
        for (int h = 0; h < 4; h++) smx[warp * 4 + h] = mx[h];
    }
    __syncthreads();
    if (tid < 4) {
        float m = fmaxf(fmaxf(smx[tid], smx[4 + tid]), fmaxf(smx[8 + tid], smx[12 + tid]));
        if (m > -1e29f) atomicMax(&g_gm1u[tid], encf(m));
    }
}

// ---------------- k_wts: per-edge softmax weights + per-node sums (warp/node) ----------------
__global__ void k_wts() {
    int warp = threadIdx.x >> 5;
    int n = blockIdx.x * 8 + warp;
    if (n >= NN) return;
    int lane = threadIdx.x & 31;
    int off = g_off[n], deg = g_off[n + 1] - off;

    const float4 adv = *(const float4*)&g_ad1[n * 4];
    float B0 = lrelu(decf(g_gm1u[0]) + adv.x);
    float B1 = lrelu(decf(g_gm1u[1]) + adv.y);
    float B2 = lrelu(decf(g_gm1u[2]) + adv.z);
    float B3 = lrelu(decf(g_gm1u[3]) + adv.w);

    float4 ws = make_float4(0.f, 0.f, 0.f, 0.f);
    for (int i = lane; i < deg; i += 32) {
        int s = g_csr[off + i];
        const float4 av = *(const float4*)&g_as1[s * 4];
        float w0 = __expf(lrelu(av.x + adv.x) - B0);
        float w1 = __expf(lrelu(av.y + adv.y) - B1);
        float w2 = __expf(lrelu(av.z + adv.z) - B2);
        float w3 = __expf(lrelu(av.w + adv.w) - B3);
        *(float4*)&g_w[(off + i) * 4] = make_float4(w0, w1, w2, w3);
        ws.x += w0; ws.y += w1; ws.z += w2; ws.w += w3;
    }
#pragma unroll
    for (int o = 16; o > 0; o >>= 1) {
        ws.x += __shfl_xor_sync(0xffffffffu, ws.x, o);
        ws.y += __shfl_xor_sync(0xffffffffu, ws.y, o);
        ws.z += __shfl_xor_sync(0xffffffffu, ws.z, o);
        ws.w += __shfl_xor_sync(0xffffffffu, ws.w, o);
    }
    if (lane == 0) *(float4*)&g_wsum[n * 4] = ws;
}

// ---------------- agg1: pure streaming gather — no smem, no barriers ----------------
__global__ void __launch_bounds__(128) k_agg1(const float* __restrict__ b1) {
    int n   = blockIdx.x;
    int tid = threadIdx.x;
    int off = g_off[n];
    int deg = g_off[n + 1] - off;
    int hf  = tid >> 5;          // head of this feature pair

    unsigned long long acc = 0ull, acc2 = 0ull;
    int j = 0;
    for (; j + 3 < deg; j += 4) {
        int s0 = g_csr[off + j],     s1 = g_csr[off + j + 1];
        int s2 = g_csr[off + j + 2], s3 = g_csr[off + j + 3];
        float w0 = g_w[(off + j) * 4 + hf];
        float w1 = g_w[(off + j + 1) * 4 + hf];
        float w2 = g_w[(off + j + 2) * 4 + hf];
        float w3 = g_w[(off + j + 3) * 4 + hf];
        unsigned long long v0 = __ldcg(&((const unsigned long long*)&g_h1[s0 * C1])[tid]);
        unsigned long long v1 = __ldcg(&((const unsigned long long*)&g_h1[s1 * C1])[tid]);
        unsigned long long v2 = __ldcg(&((const unsigned long long*)&g_h1[s2 * C1])[tid]);
        unsigned long long v3 = __ldcg(&((const unsigned long long*)&g_h1[s3 * C1])[tid]);
        acc  = fma2(v0, dup2(w0), acc);
        acc2 = fma2(v1, dup2(w1), acc2);
        acc  = fma2(v2, dup2(w2), acc);
        acc2 = fma2(v3, dup2(w3), acc2);
    }
    for (; j < deg; j++) {
        int s = g_csr[off + j];
        float w = g_w[(off + j) * 4 + hf];
        unsigned long long v = __ldcg(&((const unsigned long long*)&g_h1[s * C1])[tid]);
        acc = fma2(v, dup2(w), acc);
    }
    float ax, ay, bx, by;
    unpack2(acc, ax, ay);
    unpack2(acc2, bx, by);
    float denom = g_wsum[n * 4 + hf] + 1e-16f;

    float2 bb = ((const float2*)b1)[tid];
    float ox = (ax + bx) / denom + bb.x;
    float oy = (ay + by) / denom + bb.y;
    ox = (ox > 0.f) ? ox : expm1f(ox);
    oy = (oy > 0.f) ? oy : expm1f(oy);
    ((float2*)&g_act[n * C1])[tid] = make_float2(ox, oy);
}

// ---------------- GEMM2 + alpha2 + global-max fused (FFMA2 core) ----------------
__global__ void __launch_bounds__(256) k_gemm2(const float* __restrict__ W2,
                                               const float* __restrict__ av_s,
                                               const float* __restrict__ av_d) {
    __shared__ float sx[C1 * 32];
    __shared__ float sm8[8];
    int m0 = blockIdx.x * 32;
    int tid = threadIdx.x;
    for (int idx = tid; idx < 32 * C1; idx += 256) {
        int i = idx / C1, k = idx % C1;
        sx[k * 32 + i] = (m0 + i < NN) ? g_act[(m0 + i) * C1 + k] : 0.f;
    }
    __syncthreads();
    int col = tid & 31, ir = tid >> 5;
    unsigned long long acc01 = 0ull, acc23 = 0ull;
#pragma unroll 4
    for (int k = 0; k < C1; k++) {
        unsigned long long wd = dup2(W2[k * C2 + col]);
        unsigned long long x01 =
            *reinterpret_cast<const unsigned long long*>(&sx[k * 32 + ir * 4]);
        unsigned long long x23 =
            *reinterpret_cast<const unsigned long long*>(&sx[k * 32 + ir * 4 + 2]);
        acc01 = fma2(x01, wd, acc01);
        acc23 = fma2(x23, wd, acc23);
    }
    float acc[4];
    unpack2(acc01, acc[0], acc[1]);
    unpack2(acc23, acc[2], acc[3]);

    float s_l = av_s[col], d_l = av_d[col];
    float mx = -1e30f;
#pragma unroll
    for (int j = 0; j < 4; j++) {
        int node = m0 + ir * 4 + j;
        if (node < NN) g_h2[node * C2 + col] = acc[j];
        float ss = acc[j] * s_l, sd = acc[j] * d_l;
#pragma unroll
        for (int o = 16; o > 0; o >>= 1) {
            ss += __shfl_down_sync(0xffffffffu, ss, o);
            sd += __shfl_down_sync(0xffffffffu, sd, o);
        }
        if (col == 0 && node < NN) {
            g_as2[node] = ss;
            g_ad2[node] = sd;
            mx = fmaxf(mx, ss);
        }
    }
    if (col == 0) sm8[ir] = mx;
    __syncthreads();
    if (tid == 0) {
        float m = -1e30f;
#pragma unroll
        for (int w = 0; w < 8; w++) m = fmaxf(m, sm8[w]);
        if (m > -1e29f) atomicMax(&g_gm2u, encf(m));
    }
}

// ---------------- agg2: warp per dst node, single pass, 4-way MLP ----------------
__global__ void k_agg2(const float* __restrict__ b2, float* __restrict__ out) {
    int warp = threadIdx.x >> 5;
    int n = blockIdx.x * 8 + warp;
    if (n >= NN) return;
    int lane = threadIdx.x & 31;
    int off = g_off[n], deg = g_off[n + 1] - off;
    float adn = g_ad2[n];
    float B = lrelu(decf(g_gm2u) + adn);

    float a0 = 0.f, a1 = 0.f, a2 = 0.f, a3 = 0.f;
    float w0s = 0.f, w1s = 0.f, w2s = 0.f, w3s = 0.f;
    int i = 0;
    for (; i + 3 < deg; i += 4) {
        int s0 = g_csr[off + i],     s1 = g_csr[off + i + 1];
        int s2 = g_csr[off + i + 2], s3 = g_csr[off + i + 3];
        float w0 = __expf(lrelu(g_as2[s0] + adn) - B);
        float w1 = __expf(lrelu(g_as2[s1] + adn) - B);
        float w2 = __expf(lrelu(g_as2[s2] + adn) - B);
        float w3 = __expf(lrelu(g_as2[s3] + adn) - B);
        a0 = fmaf(__ldcg(&g_h2[s0 * C2 + lane]), w0, a0);
        a1 = fmaf(__ldcg(&g_h2[s1 * C2 + lane]), w1, a1);
        a2 = fmaf(__ldcg(&g_h2[s2 * C2 + lane]), w2, a2);
        a3 = fmaf(__ldcg(&g_h2[s3 * C2 + lane]), w3, a3);
        w0s += w0; w1s += w1; w2s += w2; w3s += w3;
    }
    for (; i < deg; i++) {
        int s = g_csr[off + i];
        float w = __expf(lrelu(g_as2[s] + adn) - B);
        a0 = fmaf(__ldcg(&g_h2[s * C2 + lane]), w, a0);
        w0s += w;
    }
    out[n * C2 + lane] = (a0 + a1 + a2 + a3) / (w0s + w1s + w2s + w3s + 1e-16f) + b2[lane];
}

// ---------------- launch: CSR build (stream 0) ∥ GEMM1 (side stream) ----------------
extern "C" void kernel_launch(void* const* d_in, const int* in_sizes, int n_in,
                              void* d_out, int out_size) {
    const float* x    = (const float*)d_in[0];
    const int*   ei   = (const int*)d_in[1];
    const float* W1   = (const float*)d_in[2];
    const float* as1v = (const float*)d_in[3];
    const float* ad1v = (const float*)d_in[4];
    const float* b1   = (const float*)d_in[5];
    const float* W2   = (const float*)d_in[6];
    const float* as2v = (const float*)d_in[7];
    const float* ad2v = (const float*)d_in[8];
    const float* b2   = (const float*)d_in[9];
    float*       out  = (float*)d_out;

    // fork: GEMM1 is independent of the CSR build
    cudaStream_t s2;
    cudaStreamCreateWithFlags(&s2, cudaStreamNonBlocking);
    cudaEvent_t eRoot, eG1;
    cudaEventCreateWithFlags(&eRoot, cudaEventDisableTiming);
    cudaEventCreateWithFlags(&eG1, cudaEventDisableTiming);

    cudaEventRecord(eRoot, 0);
    cudaStreamWaitEvent(s2, eRoot, 0);
    k_gemm1<<<(NN + 31) / 32, 128, 0, s2>>>(x, W1, as1v, ad1v);
    cudaEventRecord(eG1, s2);

    // CSR chain on the main stream
    k_zero_deg<<<(NN + 255) / 256, 256>>>(ei);   // also detects edge dtype
    k_count<<<(ETOT + 255) / 256, 256>>>(ei);
    k_scan_local<<<NB, SCAN_B>>>();
    k_scan_bsum<<<1, 128>>>();
    k_scan_add<<<NB, SCAN_B>>>();
    k_fill<<<(ETOT + 255) / 256, 256>>>(ei);

    // join, then the dependent chain
    cudaStreamWaitEvent(0, eG1, 0);
    k_wts<<<(NN + 7) / 8, 256>>>();
    k_agg1<<<NN, 128>>>(b1);
    k_gemm2<<<(NN + 31) / 32, 256>>>(W2, as2v, ad2v);
    k_agg2<<<(NN + 7) / 8, 256>>>(b2, out);
    // s2 / events intentionally leaked (host handles only; kernel_launch is
    // invoked a handful of times — correctness run + one graph capture)
}

// round 9
// speedup vs baseline: 1.7793x; 1.0249x over previous
#include <cuda_runtime.h>
#include <cuda_bf16.h>
#include <cuda_fp16.h>

#define NN   50000
#define NE   800000
#define ETOT (NE + NN)   // edges + self loops
#define IN   128
#define C1   256         // HEADS*HIDDEN
#define H1   4
#define F1   64
#define C2   32
#define SCAN_B 512
#define NB   ((NN + SCAN_B - 1) / SCAN_B)   // 98

// ---------------- scratch (static device globals; no allocation) ----------------
__device__ __half2  g_h1h[NN * 128];   // layer1 features, fp16x2 (gather-only payload)
__device__ float    g_act[NN * C1];
__device__ float    g_h2 [NN * C2];
__device__ float    g_as1[NN * H1];
__device__ float    g_ad1[NN * H1];
__device__ float    g_as2[NN];
__device__ float    g_ad2[NN];
__device__ float    g_w   [ETOT * 4];  // per-edge per-head softmax numerators
__device__ float    g_wsum[NN * 4];    // per-node per-head denominators
__device__ unsigned g_gm1u[4];
__device__ unsigned g_gm2u;
__device__ int      g_deg[NN];
__device__ int      g_off[NN + 1];
__device__ int      g_pos[NN];
__device__ int      g_bsum[128];
__device__ int      g_boff[128];
__device__ int      g_csr[ETOT];
__device__ int      g_stride;

__device__ __forceinline__ float lrelu(float v) { return v > 0.f ? v : 0.2f * v; }

__device__ __forceinline__ unsigned encf(float f) {
    unsigned u = __float_as_uint(f);
    return (u & 0x80000000u) ? ~u : (u | 0x80000000u);
}
__device__ __forceinline__ float decf(unsigned e) {
    return (e & 0x80000000u) ? __uint_as_float(e ^ 0x80000000u) : __uint_as_float(~e);
}

// packed fp32x2 helpers (FFMA2 — full fp32 precision, 2 lanes/instr)
__device__ __forceinline__ unsigned long long dup2(float v) {
    unsigned long long r;
    asm("mov.b64 %0, {%1, %1};" : "=l"(r) : "f"(v));
    return r;
}
__device__ __forceinline__ unsigned long long fma2(unsigned long long a,
                                                   unsigned long long b,
                                                   unsigned long long c) {
    unsigned long long d;
    asm("fma.rn.f32x2 %0, %1, %2, %3;" : "=l"(d) : "l"(a), "l"(b), "l"(c));
    return d;
}
__device__ __forceinline__ void unpack2(unsigned long long v, float& lo, float& hi) {
    asm("mov.b64 {%0, %1}, %2;" : "=f"(lo), "=f"(hi) : "l"(v));
}

// ---------------- zero + edge_index dtype detection (block 0) ----------------
__global__ void k_zero_deg(const int* __restrict__ p) {
    int i = blockIdx.x * blockDim.x + threadIdx.x;
    if (i < NN) g_deg[i] = 0;
    if (i < 4)  g_gm1u[i] = 0u;
    if (i == 4) g_gm2u = 0u;
    if (blockIdx.x == 0) {
        __shared__ int nz[256];
        int t = threadIdx.x;
        int acc = 0;
#pragma unroll
        for (int j = 0; j < 4; j++) acc |= p[2 * (t + 256 * j) + 1];
        nz[t] = acc;
        __syncthreads();
        for (int st = 128; st > 0; st >>= 1) {
            if (t < st) nz[t] |= nz[t + st];
            __syncthreads();
        }
        if (t == 0) g_stride = (nz[0] == 0) ? 2 : 1;
    }
}

// ---------------- CSR build ----------------
__global__ void k_count(const int* __restrict__ ei) {
    int e = blockIdx.x * blockDim.x + threadIdx.x;
    if (e >= ETOT) return;
    int st = g_stride;
    int d = (e < NE) ? ei[(NE + e) * st] : (e - NE);
    atomicAdd(&g_deg[d], 1);
}

__global__ void k_scan_local() {
    __shared__ int s[SCAN_B];
    int i = blockIdx.x * SCAN_B + threadIdx.x;
    int v = (i < NN) ? g_deg[i] : 0;
    s[threadIdx.x] = v;
    __syncthreads();
    for (int st = 1; st < SCAN_B; st <<= 1) {
        int t = (threadIdx.x >= st) ? s[threadIdx.x - st] : 0;
        __syncthreads();
        s[threadIdx.x] += t;
        __syncthreads();
    }
    if (i < NN) g_off[i] = s[threadIdx.x] - v;
    if (threadIdx.x == SCAN_B - 1) g_bsum[blockIdx.x] = s[SCAN_B - 1];
}

__global__ void k_scan_bsum() {
    __shared__ int s[128];
    int v = (threadIdx.x < NB) ? g_bsum[threadIdx.x] : 0;
    s[threadIdx.x] = v;
    __syncthreads();
    for (int st = 1; st < 128; st <<= 1) {
        int t = (threadIdx.x >= st) ? s[threadIdx.x - st] : 0;
        __syncthreads();
        s[threadIdx.x] += t;
        __syncthreads();
    }
    if (threadIdx.x < NB) g_boff[threadIdx.x] = s[threadIdx.x] - v;
}

__global__ void k_scan_add() {
    int i = blockIdx.x * SCAN_B + threadIdx.x;
    if (i < NN) {
        int o = g_off[i] + g_boff[blockIdx.x];
        g_off[i] = o;
        g_pos[i] = o;
    }
    if (i == 0) g_off[NN] = ETOT;
}

__global__ void k_fill(const int* __restrict__ ei) {
    int e = blockIdx.x * blockDim.x + threadIdx.x;
    if (e >= ETOT) return;
    int st = g_stride;
    int s, d;
    if (e < NE) { s = ei[e * st]; d = ei[(NE + e) * st]; }
    else        { s = d = e - NE; }
    int slot = atomicAdd(&g_pos[d], 1);
    g_csr[slot] = s;
}

// ---------------- GEMM1 + alpha1 + global-max fused (FFMA2 core, fp16 h1 out) ----------------
#define SXP 34
__global__ void __launch_bounds__(128) k_gemm1(const float* __restrict__ x,
                                               const float* __restrict__ W1,
                                               const float* __restrict__ av_s,
                                               const float* __restrict__ av_d) {
    __shared__ float sh[32 * 256];   // 32KB; phase A: padded x tile, phase B: out tile
    __shared__ float smx[16];
    float* sx = sh;
    int m0 = blockIdx.x * 32;
    int tid = threadIdx.x;

    for (int idx = tid; idx < 32 * IN; idx += 128) {
        int i = idx >> 7, k = idx & 127;
        sx[k * SXP + i] = (m0 + i < NN) ? x[(m0 + i) * IN + k] : 0.f;
    }
    __syncthreads();

    unsigned long long accA[16], accB[16];
#pragma unroll
    for (int j = 0; j < 16; j++) { accA[j] = 0ull; accB[j] = 0ull; }

    const float2* Wp = (const float2*)W1;
#pragma unroll 2
    for (int k = 0; k < IN; k++) {
        float2 wv = Wp[k * 128 + tid];
        unsigned long long wlo = dup2(wv.x), whi = dup2(wv.y);
#pragma unroll
        for (int j = 0; j < 16; j++) {
            unsigned long long x2 =
                *reinterpret_cast<const unsigned long long*>(&sx[k * SXP + 2 * j]);
            accA[j] = fma2(x2, wlo, accA[j]);
            accB[j] = fma2(x2, whi, accB[j]);
        }
    }
    __syncthreads();

#pragma unroll
    for (int j = 0; j < 16; j++) {
        float alo, ahi, blo, bhi;
        unpack2(accA[j], alo, ahi);
        unpack2(accB[j], blo, bhi);
        *(float2*)&sh[(2 * j)     * 256 + 2 * tid] = make_float2(alo, blo);
        *(float2*)&sh[(2 * j + 1) * 256 + 2 * tid] = make_float2(ahi, bhi);
    }
    __syncthreads();

    // coalesced fp16 store of h1 (gather payload)
#pragma unroll
    for (int r = 0; r < 16; r++) {
        int idx = r * 128 + tid;
        int node = idx >> 6, q = idx & 63;
        if (m0 + node < NN) {
            float4 v = *(float4*)&sh[node * 256 + 4 * q];
            __half2 h01 = __floats2half2_rn(v.x, v.y);
            __half2 h23 = __floats2half2_rn(v.z, v.w);
            uint2 pk;
            pk.x = *(unsigned*)&h01;
            pk.y = *(unsigned*)&h23;
            *(uint2*)&g_h1h[(m0 + node) * 128 + 2 * q] = pk;
        }
    }

    int warp = tid >> 5, lane = tid & 31;
    float a_s[8], a_d[8];
#pragma unroll
    for (int j = 0; j < 8; j++) {
        a_s[j] = av_s[lane + 32 * j];
        a_d[j] = av_d[lane + 32 * j];
    }
    float mx[4] = {-1e30f, -1e30f, -1e30f, -1e30f};
#pragma unroll
    for (int r = 0; r < 8; r++) {
        int i = warp + 4 * r;
        float ps[4] = {0.f, 0.f, 0.f, 0.f};
        float pd[4] = {0.f, 0.f, 0.f, 0.f};
#pragma unroll
        for (int j = 0; j < 8; j++) {
            float v = sh[i * 256 + lane + 32 * j];
            int h = j >> 1;
            ps[h] = fmaf(v, a_s[j], ps[h]);
            pd[h] = fmaf(v, a_d[j], pd[h]);
        }
#pragma unroll
        for (int o = 16; o > 0; o >>= 1) {
#pragma unroll
            for (int h = 0; h < 4; h++) {
                ps[h] += __shfl_down_sync(0xffffffffu, ps[h], o);
                pd[h] += __shfl_down_sync(0xffffffffu, pd[h], o);
            }
        }
        if (lane == 0 && m0 + i < NN) {
#pragma unroll
            for (int h = 0; h < 4; h++) {
                g_as1[(m0 + i) * 4 + h] = ps[h];
                g_ad1[(m0 + i) * 4 + h] = pd[h];
                mx[h] = fmaxf(mx[h], ps[h]);
            }
        }
    }
    if (lane == 0) {
#pragma unroll
        for (int h = 0; h < 4; h++) smx[warp * 4 + h] = mx[h];
    }
    __syncthreads();
    if (tid < 4) {
        float m = fmaxf(fmaxf(smx[tid], smx[4 + tid]), fmaxf(smx[8 + tid], smx[12 + tid]));
        if (m > -1e29f) atomicMax(&g_gm1u[tid], encf(m));
    }
}

// ---------------- k_wts: per-edge softmax weights + per-node sums (warp/node) ----------------
__global__ void k_wts() {
    int warp = threadIdx.x >> 5;
    int n = blockIdx.x * 8 + warp;
    if (n >= NN) return;
    int lane = threadIdx.x & 31;
    int off = g_off[n], deg = g_off[n + 1] - off;

    const float4 adv = *(const float4*)&g_ad1[n * 4];
    float B0 = lrelu(decf(g_gm1u[0]) + adv.x);
    float B1 = lrelu(decf(g_gm1u[1]) + adv.y);
    float B2 = lrelu(decf(g_gm1u[2]) + adv.z);
    float B3 = lrelu(decf(g_gm1u[3]) + adv.w);

    float4 ws = make_float4(0.f, 0.f, 0.f, 0.f);
    for (int i = lane; i < deg; i += 32) {
        int s = g_csr[off + i];
        const float4 av = *(const float4*)&g_as1[s * 4];
        float w0 = __expf(lrelu(av.x + adv.x) - B0);
        float w1 = __expf(lrelu(av.y + adv.y) - B1);
        float w2 = __expf(lrelu(av.z + adv.z) - B2);
        float w3 = __expf(lrelu(av.w + adv.w) - B3);
        *(float4*)&g_w[(off + i) * 4] = make_float4(w0, w1, w2, w3);
        ws.x += w0; ws.y += w1; ws.z += w2; ws.w += w3;
    }
#pragma unroll
    for (int o = 16; o > 0; o >>= 1) {
        ws.x += __shfl_xor_sync(0xffffffffu, ws.x, o);
        ws.y += __shfl_xor_sync(0xffffffffu, ws.y, o);
        ws.z += __shfl_xor_sync(0xffffffffu, ws.z, o);
        ws.w += __shfl_xor_sync(0xffffffffu, ws.w, o);
    }
    if (lane == 0) *(float4*)&g_wsum[n * 4] = ws;
}

// ---------------- agg1: pure streaming fp16 gather, fp32 accumulate ----------------
__global__ void __launch_bounds__(128) k_agg1(const float* __restrict__ b1) {
    int n   = blockIdx.x;
    int tid = threadIdx.x;
    int off = g_off[n];
    int deg = g_off[n + 1] - off;
    int hf  = tid >> 5;          // head of this feature pair

    float2 acc0 = make_float2(0.f, 0.f), acc1 = make_float2(0.f, 0.f);
    int j = 0;
    for (; j + 3 < deg; j += 4) {
        int s0 = g_csr[off + j],     s1 = g_csr[off + j + 1];
        int s2 = g_csr[off + j + 2], s3 = g_csr[off + j + 3];
        float w0 = g_w[(off + j) * 4 + hf];
        float w1 = g_w[(off + j + 1) * 4 + hf];
        float w2 = g_w[(off + j + 2) * 4 + hf];
        float w3 = g_w[(off + j + 3) * 4 + hf];
        float2 f0 = __half22float2(__ldcg(&g_h1h[s0 * 128 + tid]));
        float2 f1 = __half22float2(__ldcg(&g_h1h[s1 * 128 + tid]));
        float2 f2 = __half22float2(__ldcg(&g_h1h[s2 * 128 + tid]));
        float2 f3 = __half22float2(__ldcg(&g_h1h[s3 * 128 + tid]));
        acc0.x = fmaf(f0.x, w0, acc0.x); acc0.y = fmaf(f0.y, w0, acc0.y);
        acc1.x = fmaf(f1.x, w1, acc1.x); acc1.y = fmaf(f1.y, w1, acc1.y);
        acc0.x = fmaf(f2.x, w2, acc0.x); acc0.y = fmaf(f2.y, w2, acc0.y);
        acc1.x = fmaf(f3.x, w3, acc1.x); acc1.y = fmaf(f3.y, w3, acc1.y);
    }
    for (; j < deg; j++) {
        int s = g_csr[off + j];
        float w = g_w[(off + j) * 4 + hf];
        float2 f = __half22float2(__ldcg(&g_h1h[s * 128 + tid]));
        acc0.x = fmaf(f.x, w, acc0.x); acc0.y = fmaf(f.y, w, acc0.y);
    }
    float denom = g_wsum[n * 4 + hf] + 1e-16f;

    float2 bb = ((const float2*)b1)[tid];
    float ox = (acc0.x + acc1.x) / denom + bb.x;
    float oy = (acc0.y + acc1.y) / denom + bb.y;
    ox = (ox > 0.f) ? ox : expm1f(ox);
    oy = (oy > 0.f) ? oy : expm1f(oy);
    ((float2*)&g_act[n * C1])[tid] = make_float2(ox, oy);
}

// ---------------- GEMM2 + alpha2 + global-max fused (FFMA2 core) ----------------
__global__ void __launch_bounds__(256) k_gemm2(const float* __restrict__ W2,
                                               const float* __restrict__ av_s,
                                               const float* __restrict__ av_d) {
    __shared__ float sx[C1 * 32];
    __shared__ float sm8[8];
    int m0 = blockIdx.x * 32;
    int tid = threadIdx.x;
    for (int idx = tid; idx < 32 * C1; idx += 256) {
        int i = idx / C1, k = idx % C1;
        sx[k * 32 + i] = (m0 + i < NN) ? g_act[(m0 + i) * C1 + k] : 0.f;
    }
    __syncthreads();
    int col = tid & 31, ir = tid >> 5;
    unsigned long long acc01 = 0ull, acc23 = 0ull;
#pragma unroll 4
    for (int k = 0; k < C1; k++) {
        unsigned long long wd = dup2(W2[k * C2 + col]);
        unsigned long long x01 =
            *reinterpret_cast<const unsigned long long*>(&sx[k * 32 + ir * 4]);
        unsigned long long x23 =
            *reinterpret_cast<const unsigned long long*>(&sx[k * 32 + ir * 4 + 2]);
        acc01 = fma2(x01, wd, acc01);
        acc23 = fma2(x23, wd, acc23);
    }
    float acc[4];
    unpack2(acc01, acc[0], acc[1]);
    unpack2(acc23, acc[2], acc[3]);

    float s_l = av_s[col], d_l = av_d[col];
    float mx = -1e30f;
#pragma unroll
    for (int j = 0; j < 4; j++) {
        int node = m0 + ir * 4 + j;
        if (node < NN) g_h2[node * C2 + col] = acc[j];
        float ss = acc[j] * s_l, sd = acc[j] * d_l;
#pragma unroll
        for (int o = 16; o > 0; o >>= 1) {
            ss += __shfl_down_sync(0xffffffffu, ss, o);
            sd += __shfl_down_sync(0xffffffffu, sd, o);
        }
        if (col == 0 && node < NN) {
            g_as2[node] = ss;
            g_ad2[node] = sd;
            mx = fmaxf(mx, ss);
        }
    }
    if (col == 0) sm8[ir] = mx;
    __syncthreads();
    if (tid == 0) {
        float m = -1e30f;
#pragma unroll
        for (int w = 0; w < 8; w++) m = fmaxf(m, sm8[w]);
        if (m > -1e29f) atomicMax(&g_gm2u, encf(m));
    }
}

// ---------------- agg2: warp per dst node, single pass, 4-way MLP ----------------
__global__ void k_agg2(const float* __restrict__ b2, float* __restrict__ out) {
    int warp = threadIdx.x >> 5;
    int n = blockIdx.x * 8 + warp;
    if (n >= NN) return;
    int lane = threadIdx.x & 31;
    int off = g_off[n], deg = g_off[n + 1] - off;
    float adn = g_ad2[n];
    float B = lrelu(decf(g_gm2u) + adn);

    float a0 = 0.f, a1 = 0.f, a2 = 0.f, a3 = 0.f;
    float w0s = 0.f, w1s = 0.f, w2s = 0.f, w3s = 0.f;
    int i = 0;
    for (; i + 3 < deg; i += 4) {
        int s0 = g_csr[off + i],     s1 = g_csr[off + i + 1];
        int s2 = g_csr[off + i + 2], s3 = g_csr[off + i + 3];
        float w0 = __expf(lrelu(g_as2[s0] + adn) - B);
        float w1 = __expf(lrelu(g_as2[s1] + adn) - B);
        float w2 = __expf(lrelu(g_as2[s2] + adn) - B);
        float w3 = __expf(lrelu(g_as2[s3] + adn) - B);
        a0 = fmaf(__ldcg(&g_h2[s0 * C2 + lane]), w0, a0);
        a1 = fmaf(__ldcg(&g_h2[s1 * C2 + lane]), w1, a1);
        a2 = fmaf(__ldcg(&g_h2[s2 * C2 + lane]), w2, a2);
        a3 = fmaf(__ldcg(&g_h2[s3 * C2 + lane]), w3, a3);
        w0s += w0; w1s += w1; w2s += w2; w3s += w3;
    }
    for (; i < deg; i++) {
        int s = g_csr[off + i];
        float w = __expf(lrelu(g_as2[s] + adn) - B);
        a0 = fmaf(__ldcg(&g_h2[s * C2 + lane]), w, a0);
        w0s += w;
    }
    out[n * C2 + lane] = (a0 + a1 + a2 + a3) / (w0s + w1s + w2s + w3s + 1e-16f) + b2[lane];
}

// ---------------- launch: CSR build (stream 0) ∥ GEMM1 (side stream) ----------------
extern "C" void kernel_launch(void* const* d_in, const int* in_sizes, int n_in,
                              void* d_out, int out_size) {
    const float* x    = (const float*)d_in[0];
    const int*   ei   = (const int*)d_in[1];
    const float* W1   = (const float*)d_in[2];
    const float* as1v = (const float*)d_in[3];
    const float* ad1v = (const float*)d_in[4];
    const float* b1   = (const float*)d_in[5];
    const float* W2   = (const float*)d_in[6];
    const float* as2v = (const float*)d_in[7];
    const float* ad2v = (const float*)d_in[8];
    const float* b2   = (const float*)d_in[9];
    float*       out  = (float*)d_out;

    // fork: GEMM1 is independent of the CSR build
    cudaStream_t s2;
    cudaStreamCreateWithFlags(&s2, cudaStreamNonBlocking);
    cudaEvent_t eRoot, eG1;
    cudaEventCreateWithFlags(&eRoot, cudaEventDisableTiming);
    cudaEventCreateWithFlags(&eG1, cudaEventDisableTiming);

    cudaEventRecord(eRoot, 0);
    cudaStreamWaitEvent(s2, eRoot, 0);
    k_gemm1<<<(NN + 31) / 32, 128, 0, s2>>>(x, W1, as1v, ad1v);
    cudaEventRecord(eG1, s2);

    // CSR chain on the main stream
    k_zero_deg<<<(NN + 255) / 256, 256>>>(ei);   // also detects edge dtype
    k_count<<<(ETOT + 255) / 256, 256>>>(ei);
    k_scan_local<<<NB, SCAN_B>>>();
    k_scan_bsum<<<1, 128>>>();
    k_scan_add<<<NB, SCAN_B>>>();
    k_fill<<<(ETOT + 255) / 256, 256>>>(ei);

    // join, then the dependent chain
    cudaStreamWaitEvent(0, eG1, 0);
    k_wts<<<(NN + 7) / 8, 256>>>();
    k_agg1<<<NN, 128>>>(b1);
    k_gemm2<<<(NN + 31) / 32, 256>>>(W2, as2v, ad2v);
    k_agg2<<<(NN + 7) / 8, 256>>>(b2, out);
    // s2 / events intentionally leaked (host handles only; kernel_launch is
    // invoked a handful of times — correctness run + one graph capture)
}

// round 10
// speedup vs baseline: 1.9570x; 1.0999x over previous
#include <cuda_runtime.h>
#include <cuda_bf16.h>
#include <cuda_fp16.h>

#define NN   50000
#define NE   800000
#define ETOT (NE + NN)   // edges + self loops
#define IN   128
#define C1   256         // HEADS*HIDDEN
#define H1   4
#define F1   64
#define C2   32
#define SCAN_B 512
#define NB   ((NN + SCAN_B - 1) / SCAN_B)   // 98

// ---------------- scratch (static device globals; no allocation) ----------------
__device__ __half2  g_h1h[NN * 128];   // layer1 features, fp16x2 (gather-only payload)
__device__ float    g_act[NN * C1];
__device__ float    g_h2 [NN * C2];
__device__ float    g_as1[NN * H1];
__device__ float    g_ad1[NN * H1];
__device__ float    g_as2[NN];
__device__ float    g_ad2[NN];
__device__ float    g_w   [ETOT * 4];  // per-edge per-head softmax numerators
__device__ float    g_wsum[NN * 4];    // per-node per-head denominators
__device__ unsigned g_gm1u[4];
__device__ unsigned g_gm2u;
__device__ int      g_deg[NN];
__device__ int      g_off[NN + 1];
__device__ int      g_pos[NN];
__device__ int      g_bsum[128];
__device__ int      g_boff[128];
__device__ int      g_csr[ETOT];
__device__ int      g_stride;

__device__ __forceinline__ float lrelu(float v) { return v > 0.f ? v : 0.2f * v; }

__device__ __forceinline__ unsigned encf(float f) {
    unsigned u = __float_as_uint(f);
    return (u & 0x80000000u) ? ~u : (u | 0x80000000u);
}
__device__ __forceinline__ float decf(unsigned e) {
    return (e & 0x80000000u) ? __uint_as_float(e ^ 0x80000000u) : __uint_as_float(~e);
}

// packed fp32x2 helpers (FFMA2 — full fp32 precision, 2 lanes/instr)
__device__ __forceinline__ unsigned long long dup2(float v) {
    unsigned long long r;
    asm("mov.b64 %0, {%1, %1};" : "=l"(r) : "f"(v));
    return r;
}
__device__ __forceinline__ unsigned long long fma2(unsigned long long a,
                                                   unsigned long long b,
                                                   unsigned long long c) {
    unsigned long long d;
    asm("fma.rn.f32x2 %0, %1, %2, %3;" : "=l"(d) : "l"(a), "l"(b), "l"(c));
    return d;
}
__device__ __forceinline__ void unpack2(unsigned long long v, float& lo, float& hi) {
    asm("mov.b64 {%0, %1}, %2;" : "=f"(lo), "=f"(hi) : "l"(v));
}

// ---------------- zero + edge_index dtype detection (block 0) ----------------
__global__ void k_zero_deg(const int* __restrict__ p) {
    int i = blockIdx.x * blockDim.x + threadIdx.x;
    if (i < NN) g_deg[i] = 0;
    if (i < 4)  g_gm1u[i] = 0u;
    if (i == 4) g_gm2u = 0u;
    if (blockIdx.x == 0) {
        __shared__ int nz[256];
        int t = threadIdx.x;
        int acc = 0;
#pragma unroll
        for (int j = 0; j < 4; j++) acc |= p[2 * (t + 256 * j) + 1];
        nz[t] = acc;
        __syncthreads();
        for (int st = 128; st > 0; st >>= 1) {
            if (t < st) nz[t] |= nz[t + st];
            __syncthreads();
        }
        if (t == 0) g_stride = (nz[0] == 0) ? 2 : 1;
    }
}

// ---------------- CSR build ----------------
__global__ void k_count(const int* __restrict__ ei) {
    int e = blockIdx.x * blockDim.x + threadIdx.x;
    if (e >= ETOT) return;
    int st = g_stride;
    int d = (e < NE) ? ei[(NE + e) * st] : (e - NE);
    atomicAdd(&g_deg[d], 1);
}

__global__ void k_scan_local() {
    __shared__ int s[SCAN_B];
    int i = blockIdx.x * SCAN_B + threadIdx.x;
    int v = (i < NN) ? g_deg[i] : 0;
    s[threadIdx.x] = v;
    __syncthreads();
    for (int st = 1; st < SCAN_B; st <<= 1) {
        int t = (threadIdx.x >= st) ? s[threadIdx.x - st] : 0;
        __syncthreads();
        s[threadIdx.x] += t;
        __syncthreads();
    }
    if (i < NN) g_off[i] = s[threadIdx.x] - v;
    if (threadIdx.x == SCAN_B - 1) g_bsum[blockIdx.x] = s[SCAN_B - 1];
}

__global__ void k_scan_bsum() {
    __shared__ int s[128];
    int v = (threadIdx.x < NB) ? g_bsum[threadIdx.x] : 0;
    s[threadIdx.x] = v;
    __syncthreads();
    for (int st = 1; st < 128; st <<= 1) {
        int t = (threadIdx.x >= st) ? s[threadIdx.x - st] : 0;
        __syncthreads();
        s[threadIdx.x] += t;
        __syncthreads();
    }
    if (threadIdx.x < NB) g_boff[threadIdx.x] = s[threadIdx.x] - v;
}

__global__ void k_scan_add() {
    int i = blockIdx.x * SCAN_B + threadIdx.x;
    if (i < NN) {
        int o = g_off[i] + g_boff[blockIdx.x];
        g_off[i] = o;
        g_pos[i] = o;
    }
    if (i == 0) g_off[NN] = ETOT;
}

__global__ void k_fill(const int* __restrict__ ei) {
    int e = blockIdx.x * blockDim.x + threadIdx.x;
    if (e >= ETOT) return;
    int st = g_stride;
    int s, d;
    if (e < NE) { s = ei[e * st]; d = ei[(NE + e) * st]; }
    else        { s = d = e - NE; }
    int slot = atomicAdd(&g_pos[d], 1);
    g_csr[slot] = s;
}

// ---------------- GEMM1 + alpha1 + global-max fused (FFMA2 core, fp16 h1 out) ----------------
#define SXP 34
__global__ void __launch_bounds__(128) k_gemm1(const float* __restrict__ x,
                                               const float* __restrict__ W1,
                                               const float* __restrict__ av_s,
                                               const float* __restrict__ av_d) {
    __shared__ float sh[32 * 256];   // 32KB; phase A: padded x tile, phase B: out tile
    __shared__ float smx[16];
    float* sx = sh;
    int m0 = blockIdx.x * 32;
    int tid = threadIdx.x;

    for (int idx = tid; idx < 32 * IN; idx += 128) {
        int i = idx >> 7, k = idx & 127;
        sx[k * SXP + i] = (m0 + i < NN) ? x[(m0 + i) * IN + k] : 0.f;
    }
    __syncthreads();

    unsigned long long accA[16], accB[16];
#pragma unroll
    for (int j = 0; j < 16; j++) { accA[j] = 0ull; accB[j] = 0ull; }

    const float2* Wp = (const float2*)W1;
#pragma unroll 2
    for (int k = 0; k < IN; k++) {
        float2 wv = Wp[k * 128 + tid];
        unsigned long long wlo = dup2(wv.x), whi = dup2(wv.y);
#pragma unroll
        for (int j = 0; j < 16; j++) {
            unsigned long long x2 =
                *reinterpret_cast<const unsigned long long*>(&sx[k * SXP + 2 * j]);
            accA[j] = fma2(x2, wlo, accA[j]);
            accB[j] = fma2(x2, whi, accB[j]);
        }
    }
    __syncthreads();

#pragma unroll
    for (int j = 0; j < 16; j++) {
        float alo, ahi, blo, bhi;
        unpack2(accA[j], alo, ahi);
        unpack2(accB[j], blo, bhi);
        *(float2*)&sh[(2 * j)     * 256 + 2 * tid] = make_float2(alo, blo);
        *(float2*)&sh[(2 * j + 1) * 256 + 2 * tid] = make_float2(ahi, bhi);
    }
    __syncthreads();

    // coalesced fp16 store of h1 (gather payload)
#pragma unroll
    for (int r = 0; r < 16; r++) {
        int idx = r * 128 + tid;
        int node = idx >> 6, q = idx & 63;
        if (m0 + node < NN) {
            float4 v = *(float4*)&sh[node * 256 + 4 * q];
            __half2 h01 = __floats2half2_rn(v.x, v.y);
            __half2 h23 = __floats2half2_rn(v.z, v.w);
            uint2 pk;
            pk.x = *(unsigned*)&h01;
            pk.y = *(unsigned*)&h23;
            *(uint2*)&g_h1h[(m0 + node) * 128 + 2 * q] = pk;
        }
    }

    int warp = tid >> 5, lane = tid & 31;
    float a_s[8], a_d[8];
#pragma unroll
    for (int j = 0; j < 8; j++) {
        a_s[j] = av_s[lane + 32 * j];
        a_d[j] = av_d[lane + 32 * j];
    }
    float mx[4] = {-1e30f, -1e30f, -1e30f, -1e30f};
#pragma unroll
    for (int r = 0; r < 8; r++) {
        int i = warp + 4 * r;
        float ps[4] = {0.f, 0.f, 0.f, 0.f};
        float pd[4] = {0.f, 0.f, 0.f, 0.f};
#pragma unroll
        for (int j = 0; j < 8; j++) {
            float v = sh[i * 256 + lane + 32 * j];
            int h = j >> 1;
            ps[h] = fmaf(v, a_s[j], ps[h]);
            pd[h] = fmaf(v, a_d[j], pd[h]);
        }
#pragma unroll
        for (int o = 16; o > 0; o >>= 1) {
#pragma unroll
            for (int h = 0; h < 4; h++) {
                ps[h] += __shfl_down_sync(0xffffffffu, ps[h], o);
                pd[h] += __shfl_down_sync(0xffffffffu, pd[h], o);
            }
        }
        if (lane == 0 && m0 + i < NN) {
#pragma unroll
            for (int h = 0; h < 4; h++) {
                g_as1[(m0 + i) * 4 + h] = ps[h];
                g_ad1[(m0 + i) * 4 + h] = pd[h];
                mx[h] = fmaxf(mx[h], ps[h]);
            }
        }
    }
    if (lane == 0) {
#pragma unroll
        for (int h = 0; h < 4; h++) smx[warp * 4 + h] = mx[h];
    }
    __syncthreads();
    if (tid < 4) {
        float m = fmaxf(fmaxf(smx[tid], smx[4 + tid]), fmaxf(smx[8 + tid], smx[12 + tid]));
        if (m > -1e29f) atomicMax(&g_gm1u[tid], encf(m));
    }
}

// ---------------- k_wts: per-edge softmax weights + per-node sums (warp/node) ----------------
__global__ void k_wts() {
    int warp = threadIdx.x >> 5;
    int n = blockIdx.x * 8 + warp;
    if (n >= NN) return;
    int lane = threadIdx.x & 31;
    int off = g_off[n], deg = g_off[n + 1] - off;

    const float4 adv = *(const float4*)&g_ad1[n * 4];
    float B0 = lrelu(decf(g_gm1u[0]) + adv.x);
    float B1 = lrelu(decf(g_gm1u[1]) + adv.y);
    float B2 = lrelu(decf(g_gm1u[2]) + adv.z);
    float B3 = lrelu(decf(g_gm1u[3]) + adv.w);

    float4 ws = make_float4(0.f, 0.f, 0.f, 0.f);
    for (int i = lane; i < deg; i += 32) {
        int s = g_csr[off + i];
        const float4 av = *(const float4*)&g_as1[s * 4];
        float w0 = __expf(lrelu(av.x + adv.x) - B0);
        float w1 = __expf(lrelu(av.y + adv.y) - B1);
        float w2 = __expf(lrelu(av.z + adv.z) - B2);
        float w3 = __expf(lrelu(av.w + adv.w) - B3);
        *(float4*)&g_w[(off + i) * 4] = make_float4(w0, w1, w2, w3);
        ws.x += w0; ws.y += w1; ws.z += w2; ws.w += w3;
    }
#pragma unroll
    for (int o = 16; o > 0; o >>= 1) {
        ws.x += __shfl_xor_sync(0xffffffffu, ws.x, o);
        ws.y += __shfl_xor_sync(0xffffffffu, ws.y, o);
        ws.z += __shfl_xor_sync(0xffffffffu, ws.z, o);
        ws.w += __shfl_xor_sync(0xffffffffu, ws.w, o);
    }
    if (lane == 0) *(float4*)&g_wsum[n * 4] = ws;
}

// ---------------- agg1: WARP per node — 3 LDG warp-instrs per edge ----------------
// Row = 512B fp16 = one LDG.128 per warp. lane owns features [lane*8, lane*8+8),
// head = lane>>3. Weight load is one coalesced 16B-span LDG per edge.
__global__ void __launch_bounds__(256) k_agg1(const float* __restrict__ b1) {
    int warp = threadIdx.x >> 5;
    int n = blockIdx.x * 8 + warp;
    if (n >= NN) return;
    int lane = threadIdx.x & 31;
    int off = g_off[n];
    int deg = g_off[n + 1] - off;
    int hf  = lane >> 3;   // head of this lane's 8 features

    float acc[8];
#pragma unroll
    for (int q = 0; q < 8; q++) acc[q] = 0.f;

    int j = 0;
    for (; j + 3 < deg; j += 4) {
        int s0 = g_csr[off + j],     s1 = g_csr[off + j + 1];
        int s2 = g_csr[off + j + 2], s3 = g_csr[off + j + 3];
        float w0 = g_w[(off + j) * 4 + hf];
        float w1 = g_w[(off + j + 1) * 4 + hf];
        float w2 = g_w[(off + j + 2) * 4 + hf];
        float w3 = g_w[(off + j + 3) * 4 + hf];
        uint4 p0 = __ldcg((const uint4*)&g_h1h[s0 * 128 + lane * 4]);
        uint4 p1 = __ldcg((const uint4*)&g_h1h[s1 * 128 + lane * 4]);
        uint4 p2 = __ldcg((const uint4*)&g_h1h[s2 * 128 + lane * 4]);
        uint4 p3 = __ldcg((const uint4*)&g_h1h[s3 * 128 + lane * 4]);
#pragma unroll
        for (int h2i = 0; h2i < 4; h2i++) {
            float2 f0 = __half22float2(((const __half2*)&p0)[h2i]);
            float2 f1 = __half22float2(((const __half2*)&p1)[h2i]);
            float2 f2 = __half22float2(((const __half2*)&p2)[h2i]);
            float2 f3 = __half22float2(((const __half2*)&p3)[h2i]);
            acc[2 * h2i]     = fmaf(f0.x, w0, acc[2 * h2i]);
            acc[2 * h2i + 1] = fmaf(f0.y, w0, acc[2 * h2i + 1]);
            acc[2 * h2i]     = fmaf(f1.x, w1, acc[2 * h2i]);
            acc[2 * h2i + 1] = fmaf(f1.y, w1, acc[2 * h2i + 1]);
            acc[2 * h2i]     = fmaf(f2.x, w2, acc[2 * h2i]);
            acc[2 * h2i + 1] = fmaf(f2.y, w2, acc[2 * h2i + 1]);
            acc[2 * h2i]     = fmaf(f3.x, w3, acc[2 * h2i]);
            acc[2 * h2i + 1] = fmaf(f3.y, w3, acc[2 * h2i + 1]);
        }
    }
    for (; j < deg; j++) {
        int s = g_csr[off + j];
        float w = g_w[(off + j) * 4 + hf];
        uint4 p = __ldcg((const uint4*)&g_h1h[s * 128 + lane * 4]);
#pragma unroll
        for (int h2i = 0; h2i < 4; h2i++) {
            float2 f = __half22float2(((const __half2*)&p)[h2i]);
            acc[2 * h2i]     = fmaf(f.x, w, acc[2 * h2i]);
            acc[2 * h2i + 1] = fmaf(f.y, w, acc[2 * h2i + 1]);
        }
    }

    float denom = g_wsum[n * 4 + hf] + 1e-16f;
    float4 bb0 = *(const float4*)&b1[lane * 8];
    float4 bb1 = *(const float4*)&b1[lane * 8 + 4];
    float o0 = acc[0] / denom + bb0.x;
    float o1 = acc[1] / denom + bb0.y;
    float o2 = acc[2] / denom + bb0.z;
    float o3 = acc[3] / denom + bb0.w;
    float o4 = acc[4] / denom + bb1.x;
    float o5 = acc[5] / denom + bb1.y;
    float o6 = acc[6] / denom + bb1.z;
    float o7 = acc[7] / denom + bb1.w;
    o0 = (o0 > 0.f) ? o0 : expm1f(o0);
    o1 = (o1 > 0.f) ? o1 : expm1f(o1);
    o2 = (o2 > 0.f) ? o2 : expm1f(o2);
    o3 = (o3 > 0.f) ? o3 : expm1f(o3);
    o4 = (o4 > 0.f) ? o4 : expm1f(o4);
    o5 = (o5 > 0.f) ? o5 : expm1f(o5);
    o6 = (o6 > 0.f) ? o6 : expm1f(o6);
    o7 = (o7 > 0.f) ? o7 : expm1f(o7);
    *(float4*)&g_act[n * C1 + lane * 8]     = make_float4(o0, o1, o2, o3);
    *(float4*)&g_act[n * C1 + lane * 8 + 4] = make_float4(o4, o5, o6, o7);
}

// ---------------- GEMM2 + alpha2 + global-max fused (FFMA2 core) ----------------
__global__ void __launch_bounds__(256) k_gemm2(const float* __restrict__ W2,
                                               const float* __restrict__ av_s,
                                               const float* __restrict__ av_d) {
    __shared__ float sx[C1 * 32];
    __shared__ float sm8[8];
    int m0 = blockIdx.x * 32;
    int tid = threadIdx.x;
    for (int idx = tid; idx < 32 * C1; idx += 256) {
        int i = idx / C1, k = idx % C1;
        sx[k * 32 + i] = (m0 + i < NN) ? g_act[(m0 + i) * C1 + k] : 0.f;
    }
    __syncthreads();
    int col = tid & 31, ir = tid >> 5;
    unsigned long long acc01 = 0ull, acc23 = 0ull;
#pragma unroll 4
    for (int k = 0; k < C1; k++) {
        unsigned long long wd = dup2(W2[k * C2 + col]);
        unsigned long long x01 =
            *reinterpret_cast<const unsigned long long*>(&sx[k * 32 + ir * 4]);
        unsigned long long x23 =
            *reinterpret_cast<const unsigned long long*>(&sx[k * 32 + ir * 4 + 2]);
        acc01 = fma2(x01, wd, acc01);
        acc23 = fma2(x23, wd, acc23);
    }
    float acc[4];
    unpack2(acc01, acc[0], acc[1]);
    unpack2(acc23, acc[2], acc[3]);

    float s_l = av_s[col], d_l = av_d[col];
    float mx = -1e30f;
#pragma unroll
    for (int j = 0; j < 4; j++) {
        int node = m0 + ir * 4 + j;
        if (node < NN) g_h2[node * C2 + col] = acc[j];
        float ss = acc[j] * s_l, sd = acc[j] * d_l;
#pragma unroll
        for (int o = 16; o > 0; o >>= 1) {
            ss += __shfl_down_sync(0xffffffffu, ss, o);
            sd += __shfl_down_sync(0xffffffffu, sd, o);
        }
        if (col == 0 && node < NN) {
            g_as2[node] = ss;
            g_ad2[node] = sd;
            mx = fmaxf(mx, ss);
        }
    }
    if (col == 0) sm8[ir] = mx;
    __syncthreads();
    if (tid == 0) {
        float m = -1e30f;
#pragma unroll
        for (int w = 0; w < 8; w++) m = fmaxf(m, sm8[w]);
        if (m > -1e29f) atomicMax(&g_gm2u, encf(m));
    }
}

// ---------------- agg2: warp per dst node, single pass, 4-way MLP ----------------
__global__ void k_agg2(const float* __restrict__ b2, float* __restrict__ out) {
    int warp = threadIdx.x >> 5;
    int n = blockIdx.x * 8 + warp;
    if (n >= NN) return;
    int lane = threadIdx.x & 31;
    int off = g_off[n], deg = g_off[n + 1] - off;
    float adn = g_ad2[n];
    float B = lrelu(decf(g_gm2u) + adn);

    float a0 = 0.f, a1 = 0.f, a2 = 0.f, a3 = 0.f;
    float w0s = 0.f, w1s = 0.f, w2s = 0.f, w3s = 0.f;
    int i = 0;
    for (; i + 3 < deg; i += 4) {
        int s0 = g_csr[off + i],     s1 = g_csr[off + i + 1];
        int s2 = g_csr[off + i + 2], s3 = g_csr[off + i + 3];
        float w0 = __expf(lrelu(g_as2[s0] + adn) - B);
        float w1 = __expf(lrelu(g_as2[s1] + adn) - B);
        float w2 = __expf(lrelu(g_as2[s2] + adn) - B);
        float w3 = __expf(lrelu(g_as2[s3] + adn) - B);
        a0 = fmaf(__ldcg(&g_h2[s0 * C2 + lane]), w0, a0);
        a1 = fmaf(__ldcg(&g_h2[s1 * C2 + lane]), w1, a1);
        a2 = fmaf(__ldcg(&g_h2[s2 * C2 + lane]), w2, a2);
        a3 = fmaf(__ldcg(&g_h2[s3 * C2 + lane]), w3, a3);
        w0s += w0; w1s += w1; w2s += w2; w3s += w3;
    }
    for (; i < deg; i++) {
        int s = g_csr[off + i];
        float w = __expf(lrelu(g_as2[s] + adn) - B);
        a0 = fmaf(__ldcg(&g_h2[s * C2 + lane]), w, a0);
        w0s += w;
    }
    out[n * C2 + lane] = (a0 + a1 + a2 + a3) / (w0s + w1s + w2s + w3s + 1e-16f) + b2[lane];
}

// ---------------- launch: CSR build (stream 0) ∥ GEMM1 (side stream) ----------------
extern "C" void kernel_launch(void* const* d_in, const int* in_sizes, int n_in,
                              void* d_out, int out_size) {
    const float* x    = (const float*)d_in[0];
    const int*   ei   = (const int*)d_in[1];
    const float* W1   = (const float*)d_in[2];
    const float* as1v = (const float*)d_in[3];
    const float* ad1v = (const float*)d_in[4];
    const float* b1   = (const float*)d_in[5];
    const float* W2   = (const float*)d_in[6];
    const float* as2v = (const float*)d_in[7];
    const float* ad2v = (const float*)d_in[8];
    const float* b2   = (const float*)d_in[9];
    float*       out  = (float*)d_out;

    // fork: GEMM1 is independent of the CSR build
    cudaStream_t s2;
    cudaStreamCreateWithFlags(&s2, cudaStreamNonBlocking);
    cudaEvent_t eRoot, eG1;
    cudaEventCreateWithFlags(&eRoot, cudaEventDisableTiming);
    cudaEventCreateWithFlags(&eG1, cudaEventDisableTiming);

    cudaEventRecord(eRoot, 0);
    cudaStreamWaitEvent(s2, eRoot, 0);
    k_gemm1<<<(NN + 31) / 32, 128, 0, s2>>>(x, W1, as1v, ad1v);
    cudaEventRecord(eG1, s2);

    // CSR chain on the main stream
    k_zero_deg<<<(NN + 255) / 256, 256>>>(ei);   // also detects edge dtype
    k_count<<<(ETOT + 255) / 256, 256>>>(ei);
    k_scan_local<<<NB, SCAN_B>>>();
    k_scan_bsum<<<1, 128>>>();
    k_scan_add<<<NB, SCAN_B>>>();
    k_fill<<<(ETOT + 255) / 256, 256>>>(ei);

    // join, then the dependent chain
    cudaStreamWaitEvent(0, eG1, 0);
    k_wts<<<(NN + 7) / 8, 256>>>();
    k_agg1<<<(NN + 7) / 8, 256>>>(b1);
    k_gemm2<<<(NN + 31) / 32, 256>>>(W2, as2v, ad2v);
    k_agg2<<<(NN + 7) / 8, 256>>>(b2, out);
    // s2 / events intentionally leaked (host handles only; kernel_launch is
    // invoked a handful of times — correctness run + one graph capture)
}

// round 11
// speedup vs baseline: 1.9736x; 1.0085x over previous
#include <cuda_runtime.h>
#include <cuda_bf16.h>
#include <cuda_fp16.h>

#define NN   50000
#define NE   800000
#define ETOT (NE + NN)   // edges + self loops
#define IN   128
#define C1   256         // HEADS*HIDDEN
#define H1   4
#define F1   64
#define C2   32
#define SCAN_B 512
#define NB   ((NN + SCAN_B - 1) / SCAN_B)   // 98

// ---------------- scratch (static device globals; no allocation) ----------------
__device__ __half2  g_h1h[NN * 128];   // layer1 features, fp16x2 (gather-only payload)
__device__ float    g_act[NN * C1];
__device__ float    g_h2 [NN * C2];
__device__ float    g_as1[NN * H1];
__device__ float    g_ad1[NN * H1];
__device__ float    g_as2[NN];
__device__ float    g_ad2[NN];
__device__ unsigned g_gm1u[4];
__device__ unsigned g_gm2u;
__device__ int      g_deg[NN];
__device__ int      g_off[NN + 1];
__device__ int      g_pos[NN];
__device__ int      g_bsum[128];
__device__ int      g_boff[128];
__device__ int      g_csr[ETOT];
__device__ int      g_stride;

__device__ __forceinline__ float lrelu(float v) { return v > 0.f ? v : 0.2f * v; }

__device__ __forceinline__ unsigned encf(float f) {
    unsigned u = __float_as_uint(f);
    return (u & 0x80000000u) ? ~u : (u | 0x80000000u);
}
__device__ __forceinline__ float decf(unsigned e) {
    return (e & 0x80000000u) ? __uint_as_float(e ^ 0x80000000u) : __uint_as_float(~e);
}

// packed fp32x2 helpers (FFMA2 — full fp32 precision, 2 lanes/instr)
__device__ __forceinline__ unsigned long long dup2(float v) {
    unsigned long long r;
    asm("mov.b64 %0, {%1, %1};" : "=l"(r) : "f"(v));
    return r;
}
__device__ __forceinline__ unsigned long long fma2(unsigned long long a,
                                                   unsigned long long b,
                                                   unsigned long long c) {
    unsigned long long d;
    asm("fma.rn.f32x2 %0, %1, %2, %3;" : "=l"(d) : "l"(a), "l"(b), "l"(c));
    return d;
}
__device__ __forceinline__ void unpack2(unsigned long long v, float& lo, float& hi) {
    asm("mov.b64 {%0, %1}, %2;" : "=f"(lo), "=f"(hi) : "l"(v));
}

// ---------------- zero + edge_index dtype detection (block 0) ----------------
__global__ void k_zero_deg(const int* __restrict__ p) {
    int i = blockIdx.x * blockDim.x + threadIdx.x;
    if (i < NN) g_deg[i] = 0;
    if (i < 4)  g_gm1u[i] = 0u;
    if (i == 4) g_gm2u = 0u;
    if (blockIdx.x == 0) {
        __shared__ int nz[256];
        int t = threadIdx.x;
        int acc = 0;
#pragma unroll
        for (int j = 0; j < 4; j++) acc |= p[2 * (t + 256 * j) + 1];
        nz[t] = acc;
        __syncthreads();
        for (int st = 128; st > 0; st >>= 1) {
            if (t < st) nz[t] |= nz[t + st];
            __syncthreads();
        }
        if (t == 0) g_stride = (nz[0] == 0) ? 2 : 1;
    }
}

// ---------------- CSR build ----------------
__global__ void k_count(const int* __restrict__ ei) {
    int e = blockIdx.x * blockDim.x + threadIdx.x;
    if (e >= ETOT) return;
    int st = g_stride;
    int d = (e < NE) ? ei[(NE + e) * st] : (e - NE);
    atomicAdd(&g_deg[d], 1);
}

__global__ void k_scan_local() {
    __shared__ int s[SCAN_B];
    int i = blockIdx.x * SCAN_B + threadIdx.x;
    int v = (i < NN) ? g_deg[i] : 0;
    s[threadIdx.x] = v;
    __syncthreads();
    for (int st = 1; st < SCAN_B; st <<= 1) {
        int t = (threadIdx.x >= st) ? s[threadIdx.x - st] : 0;
        __syncthreads();
        s[threadIdx.x] += t;
        __syncthreads();
    }
    if (i < NN) g_off[i] = s[threadIdx.x] - v;
    if (threadIdx.x == SCAN_B - 1) g_bsum[blockIdx.x] = s[SCAN_B - 1];
}

__global__ void k_scan_bsum() {
    __shared__ int s[128];
    int v = (threadIdx.x < NB) ? g_bsum[threadIdx.x] : 0;
    s[threadIdx.x] = v;
    __syncthreads();
    for (int st = 1; st < 128; st <<= 1) {
        int t = (threadIdx.x >= st) ? s[threadIdx.x - st] : 0;
        __syncthreads();
        s[threadIdx.x] += t;
        __syncthreads();
    }
    if (threadIdx.x < NB) g_boff[threadIdx.x] = s[threadIdx.x] - v;
}

__global__ void k_scan_add() {
    int i = blockIdx.x * SCAN_B + threadIdx.x;
    if (i < NN) {
        int o = g_off[i] + g_boff[blockIdx.x];
        g_off[i] = o;
        g_pos[i] = o;
    }
    if (i == 0) g_off[NN] = ETOT;
}

__global__ void k_fill(const int* __restrict__ ei) {
    int e = blockIdx.x * blockDim.x + threadIdx.x;
    if (e >= ETOT) return;
    int st = g_stride;
    int s, d;
    if (e < NE) { s = ei[e * st]; d = ei[(NE + e) * st]; }
    else        { s = d = e - NE; }
    int slot = atomicAdd(&g_pos[d], 1);
    g_csr[slot] = s;
}

// ---------------- GEMM1 + alpha1 + global-max fused (FFMA2 core, fp16 h1 out) ----------------
#define SXP 34
__global__ void __launch_bounds__(128) k_gemm1(const float* __restrict__ x,
                                               const float* __restrict__ W1,
                                               const float* __restrict__ av_s,
                                               const float* __restrict__ av_d) {
    __shared__ float sh[32 * 256];   // 32KB; phase A: padded x tile, phase B: out tile
    __shared__ float smx[16];
    float* sx = sh;
    int m0 = blockIdx.x * 32;
    int tid = threadIdx.x;

    for (int idx = tid; idx < 32 * IN; idx += 128) {
        int i = idx >> 7, k = idx & 127;
        sx[k * SXP + i] = (m0 + i < NN) ? x[(m0 + i) * IN + k] : 0.f;
    }
    __syncthreads();

    unsigned long long accA[16], accB[16];
#pragma unroll
    for (int j = 0; j < 16; j++) { accA[j] = 0ull; accB[j] = 0ull; }

    const float2* Wp = (const float2*)W1;
#pragma unroll 2
    for (int k = 0; k < IN; k++) {
        float2 wv = Wp[k * 128 + tid];
        unsigned long long wlo = dup2(wv.x), whi = dup2(wv.y);
#pragma unroll
        for (int j = 0; j < 16; j++) {
            unsigned long long x2 =
                *reinterpret_cast<const unsigned long long*>(&sx[k * SXP + 2 * j]);
            accA[j] = fma2(x2, wlo, accA[j]);
            accB[j] = fma2(x2, whi, accB[j]);
        }
    }
    __syncthreads();

#pragma unroll
    for (int j = 0; j < 16; j++) {
        float alo, ahi, blo, bhi;
        unpack2(accA[j], alo, ahi);
        unpack2(accB[j], blo, bhi);
        *(float2*)&sh[(2 * j)     * 256 + 2 * tid] = make_float2(alo, blo);
        *(float2*)&sh[(2 * j + 1) * 256 + 2 * tid] = make_float2(ahi, bhi);
    }
    __syncthreads();

    // coalesced fp16 store of h1 (gather payload)
#pragma unroll
    for (int r = 0; r < 16; r++) {
        int idx = r * 128 + tid;
        int node = idx >> 6, q = idx & 63;
        if (m0 + node < NN) {
            float4 v = *(float4*)&sh[node * 256 + 4 * q];
            __half2 h01 = __floats2half2_rn(v.x, v.y);
            __half2 h23 = __floats2half2_rn(v.z, v.w);
            uint2 pk;
            pk.x = *(unsigned*)&h01;
            pk.y = *(unsigned*)&h23;
            *(uint2*)&g_h1h[(m0 + node) * 128 + 2 * q] = pk;
        }
    }

    int warp = tid >> 5, lane = tid & 31;
    float a_s[8], a_d[8];
#pragma unroll
    for (int j = 0; j < 8; j++) {
        a_s[j] = av_s[lane + 32 * j];
        a_d[j] = av_d[lane + 32 * j];
    }
    float mx[4] = {-1e30f, -1e30f, -1e30f, -1e30f};
#pragma unroll
    for (int r = 0; r < 8; r++) {
        int i = warp + 4 * r;
        float ps[4] = {0.f, 0.f, 0.f, 0.f};
        float pd[4] = {0.f, 0.f, 0.f, 0.f};
#pragma unroll
        for (int j = 0; j < 8; j++) {
            float v = sh[i * 256 + lane + 32 * j];
            int h = j >> 1;
            ps[h] = fmaf(v, a_s[j], ps[h]);
            pd[h] = fmaf(v, a_d[j], pd[h]);
        }
#pragma unroll
        for (int o = 16; o > 0; o >>= 1) {
#pragma unroll
            for (int h = 0; h < 4; h++) {
                ps[h] += __shfl_down_sync(0xffffffffu, ps[h], o);
                pd[h] += __shfl_down_sync(0xffffffffu, pd[h], o);
            }
        }
        if (lane == 0 && m0 + i < NN) {
#pragma unroll
            for (int h = 0; h < 4; h++) {
                g_as1[(m0 + i) * 4 + h] = ps[h];
                g_ad1[(m0 + i) * 4 + h] = pd[h];
                mx[h] = fmaxf(mx[h], ps[h]);
            }
        }
    }
    if (lane == 0) {
#pragma unroll
        for (int h = 0; h < 4; h++) smx[warp * 4 + h] = mx[h];
    }
    __syncthreads();
    if (tid < 4) {
        float m = fmaxf(fmaxf(smx[tid], smx[4 + tid]), fmaxf(smx[8 + tid], smx[12 + tid]));
        if (m > -1e29f) atomicMax(&g_gm1u[tid], encf(m));
    }
}

// ---------------- agg1: WARP per node, inline softmax weights ----------------
// Per edge: csr broadcast LDG + as1 LDG (16B span, head = lane>>3) + feature
// LDG.128. All lanes see all edges, so each lane's running wsum IS the full
// per-head denominator — no reduction needed.
__global__ void __launch_bounds__(256) k_agg1(const float* __restrict__ b1) {
    int warp = threadIdx.x >> 5;
    int n = blockIdx.x * 8 + warp;
    if (n >= NN) return;
    int lane = threadIdx.x & 31;
    int off = g_off[n];
    int deg = g_off[n + 1] - off;
    int hf  = lane >> 3;   // head of this lane's 8 features

    float adh = g_ad1[n * 4 + hf];
    float Bh  = lrelu(decf(g_gm1u[hf]) + adh);

    float acc[8];
#pragma unroll
    for (int q = 0; q < 8; q++) acc[q] = 0.f;
    float wsum = 0.f;

    int j = 0;
    for (; j + 3 < deg; j += 4) {
        int s0 = g_csr[off + j],     s1 = g_csr[off + j + 1];
        int s2 = g_csr[off + j + 2], s3 = g_csr[off + j + 3];
        float w0 = __expf(lrelu(g_as1[s0 * 4 + hf] + adh) - Bh);
        float w1 = __expf(lrelu(g_as1[s1 * 4 + hf] + adh) - Bh);
        float w2 = __expf(lrelu(g_as1[s2 * 4 + hf] + adh) - Bh);
        float w3 = __expf(lrelu(g_as1[s3 * 4 + hf] + adh) - Bh);
        uint4 p0 = __ldcg((const uint4*)&g_h1h[s0 * 128 + lane * 4]);
        uint4 p1 = __ldcg((const uint4*)&g_h1h[s1 * 128 + lane * 4]);
        uint4 p2 = __ldcg((const uint4*)&g_h1h[s2 * 128 + lane * 4]);
        uint4 p3 = __ldcg((const uint4*)&g_h1h[s3 * 128 + lane * 4]);
        wsum += w0 + w1 + w2 + w3;
#pragma unroll
        for (int h2i = 0; h2i < 4; h2i++) {
            float2 f0 = __half22float2(((const __half2*)&p0)[h2i]);
            float2 f1 = __half22float2(((const __half2*)&p1)[h2i]);
            float2 f2 = __half22float2(((const __half2*)&p2)[h2i]);
            float2 f3 = __half22float2(((const __half2*)&p3)[h2i]);
            acc[2 * h2i]     = fmaf(f0.x, w0, acc[2 * h2i]);
            acc[2 * h2i + 1] = fmaf(f0.y, w0, acc[2 * h2i + 1]);
            acc[2 * h2i]     = fmaf(f1.x, w1, acc[2 * h2i]);
            acc[2 * h2i + 1] = fmaf(f1.y, w1, acc[2 * h2i + 1]);
            acc[2 * h2i]     = fmaf(f2.x, w2, acc[2 * h2i]);
            acc[2 * h2i + 1] = fmaf(f2.y, w2, acc[2 * h2i + 1]);
            acc[2 * h2i]     = fmaf(f3.x, w3, acc[2 * h2i]);
            acc[2 * h2i + 1] = fmaf(f3.y, w3, acc[2 * h2i + 1]);
        }
    }
    for (; j < deg; j++) {
        int s = g_csr[off + j];
        float w = __expf(lrelu(g_as1[s * 4 + hf] + adh) - Bh);
        uint4 p = __ldcg((const uint4*)&g_h1h[s * 128 + lane * 4]);
        wsum += w;
#pragma unroll
        for (int h2i = 0; h2i < 4; h2i++) {
            float2 f = __half22float2(((const __half2*)&p)[h2i]);
            acc[2 * h2i]     = fmaf(f.x, w, acc[2 * h2i]);
            acc[2 * h2i + 1] = fmaf(f.y, w, acc[2 * h2i + 1]);
        }
    }

    float denom = wsum + 1e-16f;
    float4 bb0 = *(const float4*)&b1[lane * 8];
    float4 bb1 = *(const float4*)&b1[lane * 8 + 4];
    float o0 = acc[0] / denom + bb0.x;
    float o1 = acc[1] / denom + bb0.y;
    float o2 = acc[2] / denom + bb0.z;
    float o3 = acc[3] / denom + bb0.w;
    float o4 = acc[4] / denom + bb1.x;
    float o5 = acc[5] / denom + bb1.y;
    float o6 = acc[6] / denom + bb1.z;
    float o7 = acc[7] / denom + bb1.w;
    o0 = (o0 > 0.f) ? o0 : expm1f(o0);
    o1 = (o1 > 0.f) ? o1 : expm1f(o1);
    o2 = (o2 > 0.f) ? o2 : expm1f(o2);
    o3 = (o3 > 0.f) ? o3 : expm1f(o3);
    o4 = (o4 > 0.f) ? o4 : expm1f(o4);
    o5 = (o5 > 0.f) ? o5 : expm1f(o5);
    o6 = (o6 > 0.f) ? o6 : expm1f(o6);
    o7 = (o7 > 0.f) ? o7 : expm1f(o7);
    *(float4*)&g_act[n * C1 + lane * 8]     = make_float4(o0, o1, o2, o3);
    *(float4*)&g_act[n * C1 + lane * 8 + 4] = make_float4(o4, o5, o6, o7);
}

// ---------------- GEMM2 + alpha2 + global-max fused (FFMA2 core) ----------------
__global__ void __launch_bounds__(256) k_gemm2(const float* __restrict__ W2,
                                               const float* __restrict__ av_s,
                                               const float* __restrict__ av_d) {
    __shared__ float sx[C1 * 32];
    __shared__ float sm8[8];
    int m0 = blockIdx.x * 32;
    int tid = threadIdx.x;
    for (int idx = tid; idx < 32 * C1; idx += 256) {
        int i = idx / C1, k = idx % C1;
        sx[k * 32 + i] = (m0 + i < NN) ? g_act[(m0 + i) * C1 + k] : 0.f;
    }
    __syncthreads();
    int col = tid & 31, ir = tid >> 5;
    unsigned long long acc01 = 0ull, acc23 = 0ull;
#pragma unroll 4
    for (int k = 0; k < C1; k++) {
        unsigned long long wd = dup2(W2[k * C2 + col]);
        unsigned long long x01 =
            *reinterpret_cast<const unsigned long long*>(&sx[k * 32 + ir * 4]);
        unsigned long long x23 =
            *reinterpret_cast<const unsigned long long*>(&sx[k * 32 + ir * 4 + 2]);
        acc01 = fma2(x01, wd, acc01);
        acc23 = fma2(x23, wd, acc23);
    }
    float acc[4];
    unpack2(acc01, acc[0], acc[1]);
    unpack2(acc23, acc[2], acc[3]);

    float s_l = av_s[col], d_l = av_d[col];
    float mx = -1e30f;
#pragma unroll
    for (int j = 0; j < 4; j++) {
        int node = m0 + ir * 4 + j;
        if (node < NN) g_h2[node * C2 + col] = acc[j];
        float ss = acc[j] * s_l, sd = acc[j] * d_l;
#pragma unroll
        for (int o = 16; o > 0; o >>= 1) {
            ss += __shfl_down_sync(0xffffffffu, ss, o);
            sd += __shfl_down_sync(0xffffffffu, sd, o);
        }
        if (col == 0 && node < NN) {
            g_as2[node] = ss;
            g_ad2[node] = sd;
            mx = fmaxf(mx, ss);
        }
    }
    if (col == 0) sm8[ir] = mx;
    __syncthreads();
    if (tid == 0) {
        float m = -1e30f;
#pragma unroll
        for (int w = 0; w < 8; w++) m = fmaxf(m, sm8[w]);
        if (m > -1e29f) atomicMax(&g_gm2u, encf(m));
    }
}

// ---------------- agg2: warp per dst node, single pass, 4-way MLP ----------------
__global__ void k_agg2(const float* __restrict__ b2, float* __restrict__ out) {
    int warp = threadIdx.x >> 5;
    int n = blockIdx.x * 8 + warp;
    if (n >= NN) return;
    int lane = threadIdx.x & 31;
    int off = g_off[n], deg = g_off[n + 1] - off;
    float adn = g_ad2[n];
    float B = lrelu(decf(g_gm2u) + adn);

    float a0 = 0.f, a1 = 0.f, a2 = 0.f, a3 = 0.f;
    float w0s = 0.f, w1s = 0.f, w2s = 0.f, w3s = 0.f;
    int i = 0;
    for (; i + 3 < deg; i += 4) {
        int s0 = g_csr[off + i],     s1 = g_csr[off + i + 1];
        int s2 = g_csr[off + i + 2], s3 = g_csr[off + i + 3];
        float w0 = __expf(lrelu(g_as2[s0] + adn) - B);
        float w1 = __expf(lrelu(g_as2[s1] + adn) - B);
        float w2 = __expf(lrelu(g_as2[s2] + adn) - B);
        float w3 = __expf(lrelu(g_as2[s3] + adn) - B);
        a0 = fmaf(__ldcg(&g_h2[s0 * C2 + lane]), w0, a0);
        a1 = fmaf(__ldcg(&g_h2[s1 * C2 + lane]), w1, a1);
        a2 = fmaf(__ldcg(&g_h2[s2 * C2 + lane]), w2, a2);
        a3 = fmaf(__ldcg(&g_h2[s3 * C2 + lane]), w3, a3);
        w0s += w0; w1s += w1; w2s += w2; w3s += w3;
    }
    for (; i < deg; i++) {
        int s = g_csr[off + i];
        float w = __expf(lrelu(g_as2[s] + adn) - B);
        a0 = fmaf(__ldcg(&g_h2[s * C2 + lane]), w, a0);
        w0s += w;
    }
    out[n * C2 + lane] = (a0 + a1 + a2 + a3) / (w0s + w1s + w2s + w3s + 1e-16f) + b2[lane];
}

// ---------------- launch: CSR build (stream 0) ∥ GEMM1 (side stream) ----------------
extern "C" void kernel_launch(void* const* d_in, const int* in_sizes, int n_in,
                              void* d_out, int out_size) {
    const float* x    = (const float*)d_in[0];
    const int*   ei   = (const int*)d_in[1];
    const float* W1   = (const float*)d_in[2];
    const float* as1v = (const float*)d_in[3];
    const float* ad1v = (const float*)d_in[4];
    const float* b1   = (const float*)d_in[5];
    const float* W2   = (const float*)d_in[6];
    const float* as2v = (const float*)d_in[7];
    const float* ad2v = (const float*)d_in[8];
    const float* b2   = (const float*)d_in[9];
    float*       out  = (float*)d_out;

    // fork: GEMM1 is independent of the CSR build
    cudaStream_t s2;
    cudaStreamCreateWithFlags(&s2, cudaStreamNonBlocking);
    cudaEvent_t eRoot, eG1;
    cudaEventCreateWithFlags(&eRoot, cudaEventDisableTiming);
    cudaEventCreateWithFlags(&eG1, cudaEventDisableTiming);

    cudaEventRecord(eRoot, 0);
    cudaStreamWaitEvent(s2, eRoot, 0);
    k_gemm1<<<(NN + 31) / 32, 128, 0, s2>>>(x, W1, as1v, ad1v);
    cudaEventRecord(eG1, s2);

    // CSR chain on the main stream
    k_zero_deg<<<(NN + 255) / 256, 256>>>(ei);   // also detects edge dtype
    k_count<<<(ETOT + 255) / 256, 256>>>(ei);
    k_scan_local<<<NB, SCAN_B>>>();
    k_scan_bsum<<<1, 128>>>();
    k_scan_add<<<NB, SCAN_B>>>();
    k_fill<<<(ETOT + 255) / 256, 256>>>(ei);

    // join, then the dependent chain
    cudaStreamWaitEvent(0, eG1, 0);
    k_agg1<<<(NN + 7) / 8, 256>>>(b1);
    k_gemm2<<<(NN + 31) / 32, 256>>>(W2, as2v, ad2v);
    k_agg2<<<(NN + 7) / 8, 256>>>(b2, out);
    // s2 / events intentionally leaked (host handles only; kernel_launch is
    // invoked a handful of times — correctness run + one graph capture)
}